// round 6
// baseline (speedup 1.0000x reference)
#include <cuda_runtime.h>
#include <cuda_bf16.h>

// ---------------- problem constants ----------------
#define BN 8192
#define TN 223
#define DN 7
#define HN 128
#define EN 50
#define ON 29
#define AN 9
#define NTHR 256
#define NBLK 512            // 512 blocks * 16 elements = 8192

// output layout (float32): x_loss, y_loss, loss, y_h[B][O], imputations[B][T][D], labels[B]
#define YH_OFF 3
#define IMP_OFF (3 + BN*ON)
#define LBL_OFF (IMP_OFF + BN*TN*DN)

// ---------------- device scratch (static: no allocation) ----------------
__device__ float4 g_W4h[HN][HN];     // [k][j] -> (Wi,Wf,Wg,Wo)[gate*128+j][k] for h part
__device__ float4 g_W4i[2*DN][HN];   // [kc][j] for input part (c_c(7), m(7))
__device__ float4 g_b4[HN];          // per-j combined gate biases
__device__ float  g_part[4][TN];     // per-timestep global partials: msum, l1, l2, l3
__device__ float  g_yloss;

// ---------------- helpers ----------------
union F2U { float2 f; unsigned long long u; };

__device__ __forceinline__ float2 f2fma(float2 a, float2 b, float2 c) {
    F2U A, B, C, R; A.f = a; B.f = b; C.f = c;
    asm("fma.rn.f32x2 %0, %1, %2, %3;" : "=l"(R.u) : "l"(A.u), "l"(B.u), "l"(C.u));
    return R.f;
}
__device__ __forceinline__ float sig1(float x) { return __fdividef(1.f, 1.f + __expf(-x)); }
__device__ __forceinline__ float th1(float x)  { return 1.f - __fdividef(2.f, __expf(2.f * x) + 1.f); }

__device__ __forceinline__ void fma4(float2* acc, float w,
                                     float2 h0, float2 h1, float2 h2, float2 h3) {
    float2 wb = make_float2(w, w);
    acc[0] = f2fma(wb, h0, acc[0]);
    acc[1] = f2fma(wb, h1, acc[1]);
    acc[2] = f2fma(wb, h2, acc[2]);
    acc[3] = f2fma(wb, h3, acc[3]);
}

// ---------------- prep: pack gate weights, zero scratch ----------------
__global__ void rits_prep(const float* __restrict__ W_ih, const float* __restrict__ W_hh,
                          const float* __restrict__ b_ih, const float* __restrict__ b_hh) {
    int i = blockIdx.x * blockDim.x + threadIdx.x;   // grid covers 16384
    if (i < HN * HN) {
        int k = i >> 7, j = i & (HN - 1);
        g_W4h[k][j] = make_float4(W_hh[j*HN + k],        W_hh[(HN + j)*HN + k],
                                  W_hh[(2*HN + j)*HN + k], W_hh[(3*HN + j)*HN + k]);
    }
    if (i < 2*DN*HN) {
        int kc = i >> 7, j = i & (HN - 1);
        g_W4i[kc][j] = make_float4(W_ih[j*2*DN + kc],        W_ih[(HN + j)*2*DN + kc],
                                   W_ih[(2*HN + j)*2*DN + kc], W_ih[(3*HN + j)*2*DN + kc]);
    }
    if (i < HN) {
        g_b4[i] = make_float4(b_ih[i]        + b_hh[i],
                              b_ih[HN + i]   + b_hh[HN + i],
                              b_ih[2*HN + i] + b_hh[2*HN + i],
                              b_ih[3*HN + i] + b_hh[3*HN + i]);
    }
    if (i < 4 * TN) ((float*)g_part)[i] = 0.f;
    if (i == 0) g_yloss = 0.f;
}

// ---------------- main recurrence + head ----------------
__global__ void __launch_bounds__(NTHR, 4) rits_main(
    const float* __restrict__ values,  const float* __restrict__ masks,
    const float* __restrict__ deltas,  const float* __restrict__ probs,
    const float* __restrict__ ancillary, const int* __restrict__ labels,
    const float* __restrict__ W_td_h,  const float* __restrict__ b_td_h,
    const float* __restrict__ W_td_x,  const float* __restrict__ b_td_x,
    const float* __restrict__ W_hist,  const float* __restrict__ b_hist,
    const float* __restrict__ W_feat,  const float* __restrict__ b_feat,
    const float* __restrict__ W_comb,  const float* __restrict__ b_comb,
    const float* __restrict__ W_anc,   const float* __restrict__ b_anc,
    const float* __restrict__ W_cat,   const float* __restrict__ b_cat,
    const float* __restrict__ W_out,   const float* __restrict__ b_out,
    float* __restrict__ out)
{
    __shared__ __align__(16) float2 sh_h[2][HN][8];     // double-buffered hidden state
    __shared__ __align__(16) float2 sh_x[DN][8], sh_m[DN][8], sh_d[DN][8], sh_gx[DN][8];
    __shared__ __align__(16) float2 sh_xh[DN][8], sh_xc[DN][8], sh_cc[DN][8];
    __shared__ float sh_WhT[HN*DN];                     // [j*7+k] = W_hist[k][j]
    __shared__ float sh_Wtdh[HN*DN], sh_btdh[HN];
    __shared__ float sh_Wf[DN*DN], sh_Wcb[DN*2*DN];
    __shared__ float sh_bh[DN], sh_bf[DN], sh_bc[DN], sh_tdx[DN], sh_btdx[DN];
    __shared__ float sh_red[4];
    __shared__ float sh_anc[EN][16];
    __shared__ float sh_lg[ON][16];

    const int tid  = threadIdx.x;
    const int j    = tid >> 1;          // hidden unit
    const int half = tid & 1;           // element-pair half (pairs 4*half .. 4*half+3)
    const int eb   = blockIdx.x * 16;   // first element of this block

    // ---- preload small weights into shared ----
    for (int i = tid; i < HN*DN; i += NTHR) {
        int jj = i / DN, kk = i - jj * DN;
        sh_WhT[i]  = W_hist[kk * HN + jj];
        sh_Wtdh[i] = W_td_h[i];
    }
    for (int i = tid; i < HN; i += NTHR) sh_btdh[i] = b_td_h[i];
    if (tid < DN*DN) {
        int a = tid / DN, b = tid % DN;
        sh_Wf[tid] = (a == b) ? 0.f : W_feat[tid];       // zero-diagonal feature reg
    }
    if (tid < DN*2*DN) sh_Wcb[tid] = W_comb[tid];
    if (tid < DN) {
        sh_bh[tid]   = b_hist[tid];
        sh_bf[tid]   = b_feat[tid];
        sh_bc[tid]   = b_comb[tid];
        sh_tdx[tid]  = W_td_x[tid * DN + tid];           // diagonal only
        sh_btdx[tid] = b_td_x[tid];
    }
    for (int i = tid; i < HN*8; i += NTHR)
        ((float2*)sh_h)[i] = make_float2(0.f, 0.f);      // h0 = 0 (buffer 0)

    float2 cst[4];                                       // cell state, pairs 4*half+i
#pragma unroll
    for (int i = 0; i < 4; i++) cst[i] = make_float2(0.f, 0.f);

    // small-phase mapping: tid<56 -> (k=tid>>3, p=tid&7)
    const int  sk  = tid >> 3;
    const int  sp  = tid & 7;
    const bool act = (tid < 56);
    const size_t ebase0 = act ? ((size_t)(eb + 2*sp) * TN) * DN + sk : 0;
    const size_t ebase1 = ebase0 + (size_t)TN * DN;

    __syncthreads();

    for (int t = 0; t < TN; ++t) {
        const int fb = t & 1, nb = fb ^ 1;

        // ---- Phase A: load x,m,d; gamma_x ----
        if (act) {
            size_t o0 = ebase0 + (size_t)t * DN;
            size_t o1 = ebase1 + (size_t)t * DN;
            float x0 = values[o0], x1 = values[o1];
            float m0 = masks[o0],  m1 = masks[o1];
            float d0 = deltas[o0], d1 = deltas[o1];
            sh_x[sk][sp] = make_float2(x0, x1);
            sh_m[sk][sp] = make_float2(m0, m1);
            sh_d[sk][sp] = make_float2(d0, d1);
            float td = sh_tdx[sk], bx = sh_btdx[sk];
            sh_gx[sk][sp] = make_float2(__expf(-fmaxf(d0*td + bx, 0.f)),
                                        __expf(-fmaxf(d1*td + bx, 0.f)));
        } else if (tid < 60) {
            sh_red[tid - 56] = 0.f;
        }
        __syncthreads();

        // ---- Phase B: decay h in place ----
        {
            float bt = sh_btdh[j];
            float2 ga[4];
#pragma unroll
            for (int i = 0; i < 4; i++) ga[i] = make_float2(bt, bt);
#pragma unroll
            for (int kk = 0; kk < DN; kk++) {
                float  wv = sh_Wtdh[j*DN + kk];
                float2 wb = make_float2(wv, wv);
#pragma unroll
                for (int i = 0; i < 4; i++)
                    ga[i] = f2fma(wb, sh_d[kk][4*half + i], ga[i]);
            }
#pragma unroll
            for (int i = 0; i < 4; i++) {
                int p = 4*half + i;
                float2 h2 = sh_h[fb][j][p];
                sh_h[fb][j][p] = make_float2(h2.x * __expf(-fmaxf(ga[i].x, 0.f)),
                                             h2.y * __expf(-fmaxf(ga[i].y, 0.f)));
            }
        }
        __syncthreads();

        // ---- Phase C: x_h, x_c, loss1, msum ----
        float l1 = 0.f, l2 = 0.f, l3 = 0.f, msp = 0.f;
        if (act) {
            float2 a = make_float2(sh_bh[sk], sh_bh[sk]);
#pragma unroll 8
            for (int jj = 0; jj < HN; jj++) {
                float w = sh_WhT[jj*DN + sk];
                a = f2fma(make_float2(w, w), sh_h[fb][jj][sp], a);
            }
            float2 x = sh_x[sk][sp], m = sh_m[sk][sp];
            l1  = m.x * fabsf(x.x - a.x) + m.y * fabsf(x.y - a.y);
            msp = m.x + m.y;
            sh_xh[sk][sp] = a;
            sh_xc[sk][sp] = make_float2(m.x*x.x + (1.f - m.x)*a.x,
                                        m.y*x.y + (1.f - m.y)*a.y);
        }
        __syncthreads();

        // ---- Phase D: z_h, alpha, c_h, c_c, losses, imputation ----
        if (act) {
            float2 x  = sh_x[sk][sp], m = sh_m[sk][sp], xh = sh_xh[sk][sp];
            float2 z  = make_float2(sh_bf[sk], sh_bf[sk]);
#pragma unroll
            for (int k2 = 0; k2 < DN; k2++) {
                float w = sh_Wf[sk*DN + k2];
                z = f2fma(make_float2(w, w), sh_xc[k2][sp], z);
            }
            l2 = m.x * fabsf(x.x - z.x) + m.y * fabsf(x.y - z.y);
            float2 al = make_float2(sh_bc[sk], sh_bc[sk]);
#pragma unroll
            for (int k2 = 0; k2 < DN; k2++) {
                float w = sh_Wcb[sk*2*DN + k2];
                al = f2fma(make_float2(w, w), sh_gx[k2][sp], al);
            }
#pragma unroll
            for (int k2 = 0; k2 < DN; k2++) {
                float w = sh_Wcb[sk*2*DN + DN + k2];
                al = f2fma(make_float2(w, w), sh_m[k2][sp], al);
            }
            float2 ch = make_float2(al.x*z.x + (1.f - al.x)*xh.x,
                                    al.y*z.y + (1.f - al.y)*xh.y);
            l3 = m.x * fabsf(x.x - ch.x) + m.y * fabsf(x.y - ch.y);
            float2 cc = make_float2(m.x*x.x + (1.f - m.x)*ch.x,
                                    m.y*x.y + (1.f - m.y)*ch.y);
            sh_cc[sk][sp] = cc;
            size_t o0 = ebase0 + (size_t)t * DN;
            size_t o1 = ebase1 + (size_t)t * DN;
            out[IMP_OFF + o0] = cc.x;
            out[IMP_OFF + o1] = cc.y;
            atomicAdd(&sh_red[0], msp);
            atomicAdd(&sh_red[1], l1);
            atomicAdd(&sh_red[2], l2);
            atomicAdd(&sh_red[3], l3);
        }
        __syncthreads();

        if (tid == 0) {
            atomicAdd(&g_part[0][t], sh_red[0]);
            atomicAdd(&g_part[1][t], sh_red[1]);
            atomicAdd(&g_part[2][t], sh_red[2]);
            atomicAdd(&g_part[3][t], sh_red[3]);
        }

        // ---- Phase E: gate GEMM (FFMA2) + LSTM pointwise ----
        {
            float4 bias4 = g_b4[j];
            float2 acc[4][4];                 // [gate][pair]
#pragma unroll
            for (int i = 0; i < 4; i++) {
                acc[0][i] = make_float2(bias4.x, bias4.x);
                acc[1][i] = make_float2(bias4.y, bias4.y);
                acc[2][i] = make_float2(bias4.z, bias4.z);
                acc[3][i] = make_float2(bias4.w, bias4.w);
            }
            const float2* hrow = &sh_h[fb][0][4*half];
#pragma unroll 4
            for (int k = 0; k < HN; k++) {
                float4 w  = g_W4h[k][j];
                float4 ha = *(const float4*)(hrow + (size_t)k * 8);
                float4 hb = *(const float4*)(hrow + (size_t)k * 8 + 2);
                float2 h0 = make_float2(ha.x, ha.y), h1 = make_float2(ha.z, ha.w);
                float2 h2 = make_float2(hb.x, hb.y), h3 = make_float2(hb.z, hb.w);
                fma4(acc[0], w.x, h0, h1, h2, h3);
                fma4(acc[1], w.y, h0, h1, h2, h3);
                fma4(acc[2], w.z, h0, h1, h2, h3);
                fma4(acc[3], w.w, h0, h1, h2, h3);
            }
#pragma unroll
            for (int kc = 0; kc < DN; kc++) {
                float4 w  = g_W4i[kc][j];
                const float2* cr = &sh_cc[kc][4*half];
                float4 ca = *(const float4*)cr;
                float4 cb = *(const float4*)(cr + 2);
                float2 h0 = make_float2(ca.x, ca.y), h1 = make_float2(ca.z, ca.w);
                float2 h2 = make_float2(cb.x, cb.y), h3 = make_float2(cb.z, cb.w);
                fma4(acc[0], w.x, h0, h1, h2, h3);
                fma4(acc[1], w.y, h0, h1, h2, h3);
                fma4(acc[2], w.z, h0, h1, h2, h3);
                fma4(acc[3], w.w, h0, h1, h2, h3);
            }
#pragma unroll
            for (int kc = 0; kc < DN; kc++) {
                float4 w  = g_W4i[DN + kc][j];
                const float2* mr = &sh_m[kc][4*half];
                float4 ca = *(const float4*)mr;
                float4 cb = *(const float4*)(mr + 2);
                float2 h0 = make_float2(ca.x, ca.y), h1 = make_float2(ca.z, ca.w);
                float2 h2 = make_float2(cb.x, cb.y), h3 = make_float2(cb.z, cb.w);
                fma4(acc[0], w.x, h0, h1, h2, h3);
                fma4(acc[1], w.y, h0, h1, h2, h3);
                fma4(acc[2], w.z, h0, h1, h2, h3);
                fma4(acc[3], w.w, h0, h1, h2, h3);
            }
            // pointwise LSTM update
#pragma unroll
            for (int i = 0; i < 4; i++) {
                float igx = sig1(acc[0][i].x), igy = sig1(acc[0][i].y);
                float fgx = sig1(acc[1][i].x), fgy = sig1(acc[1][i].y);
                float ggx = th1(acc[2][i].x),  ggy = th1(acc[2][i].y);
                float ogx = sig1(acc[3][i].x), ogy = sig1(acc[3][i].y);
                cst[i] = make_float2(fgx * cst[i].x + igx * ggx,
                                     fgy * cst[i].y + igy * ggy);
                sh_h[nb][j][4*half + i] = make_float2(ogx * th1(cst[i].x),
                                                      ogy * th1(cst[i].y));
            }
        }
        __syncthreads();
    }

    // ================= head (final h is in sh_h[1], TN odd) =================
    // ancillary features
    for (int u = tid; u < 16 * EN; u += NTHR) {
        int e = u & 15, q = u >> 4;
        const float* ar = ancillary + (size_t)(eb + e) * AN;
        float a = b_anc[q];
#pragma unroll
        for (int k = 0; k < AN; k++) a += ar[k] * W_anc[q*AN + k];
        sh_anc[q][e] = fmaxf(a, 0.f);
    }
    __syncthreads();

    // hcat = relu([h, anc] @ W_cat^T + b_cat) -> reuse sh_h[0] as [128][16] floats
    float* sh_hc = (float*)&sh_h[0][0][0];
    {
        const float* wc = W_cat + (size_t)j * (HN + EN);
        float2 accp[4];
        float  bc = b_cat[j];
#pragma unroll
        for (int i = 0; i < 4; i++) accp[i] = make_float2(bc, bc);
        for (int jj = 0; jj < HN; jj++) {
            float  w  = wc[jj];
            float2 wb = make_float2(w, w);
#pragma unroll
            for (int i = 0; i < 4; i++)
                accp[i] = f2fma(wb, sh_h[1][jj][4*half + i], accp[i]);
        }
        for (int q = 0; q < EN; q++) {
            float w = wc[HN + q];
#pragma unroll
            for (int i = 0; i < 4; i++) {
                accp[i].x += w * sh_anc[q][8*half + 2*i];
                accp[i].y += w * sh_anc[q][8*half + 2*i + 1];
            }
        }
#pragma unroll
        for (int i = 0; i < 4; i++) {
            sh_hc[j*16 + 8*half + 2*i]     = fmaxf(accp[i].x, 0.f);
            sh_hc[j*16 + 8*half + 2*i + 1] = fmaxf(accp[i].y, 0.f);
        }
    }
    __syncthreads();

    // logits
    for (int u = tid; u < 16 * ON; u += NTHR) {
        int e = u & 15, o = u >> 4;
        const float* wo = W_out + (size_t)o * HN;
        float a = b_out[o];
#pragma unroll 8
        for (int jj = 0; jj < HN; jj++) a += sh_hc[jj*16 + e] * wo[jj];
        sh_lg[o][e] = a;
    }
    __syncthreads();

    // softmax, y_h, y_loss partial, labels copy
    if (tid < 16) {
        int e = tid;
        float mx = -1e30f;
        for (int o = 0; o < ON; o++) mx = fmaxf(mx, sh_lg[o][e]);
        float s = 0.f;
        for (int o = 0; o < ON; o++) s += __expf(sh_lg[o][e] - mx);
        float inv = __fdividef(1.f, s);
        const float* pr = probs + (size_t)(eb + e) * ON;
        float* yo = out + YH_OFF + (size_t)(eb + e) * ON;
        float yl = 0.f;
        for (int o = 0; o < ON; o++) {
            float y = __expf(sh_lg[o][e] - mx) * inv;
            yo[o] = y;
            float dd = y - pr[o];
            yl += dd * dd;
        }
        atomicAdd(&g_yloss, yl);
        out[LBL_OFF + eb + e] = (float)labels[eb + e];
    }
}

// ---------------- finalize: assemble scalars ----------------
__global__ void rits_finalize(float* __restrict__ out) {
    __shared__ float s[NTHR];
    int t = threadIdx.x;
    float v = 0.f;
    if (t < TN)
        v = (g_part[1][t] + g_part[2][t] + g_part[3][t]) / (g_part[0][t] + 1e-5f);
    s[t] = v;
    __syncthreads();
    for (int st = NTHR/2; st > 0; st >>= 1) {
        if (t < st) s[t] += s[t + st];
        __syncthreads();
    }
    if (t == 0) {
        float xl = 0.3f * s[0];                    // IMPUTE_W
        float yl = g_yloss / (8192.0f + 1e-5f);    // LABEL_W = 1
        out[0] = xl;
        out[1] = yl;
        out[2] = xl + yl;
    }
}

// ---------------- launcher ----------------
extern "C" void kernel_launch(void* const* d_in, const int* in_sizes, int n_in,
                              void* d_out, int out_size) {
    (void)in_sizes; (void)n_in; (void)out_size;
    const float* values    = (const float*)d_in[0];
    const float* masks     = (const float*)d_in[1];
    const float* deltas    = (const float*)d_in[2];
    const float* probs     = (const float*)d_in[3];
    const float* ancillary = (const float*)d_in[4];
    const int*   labels    = (const int*)  d_in[5];
    const float* W_td_h = (const float*)d_in[6];
    const float* b_td_h = (const float*)d_in[7];
    const float* W_td_x = (const float*)d_in[8];
    const float* b_td_x = (const float*)d_in[9];
    const float* W_hist = (const float*)d_in[10];
    const float* b_hist = (const float*)d_in[11];
    const float* W_feat = (const float*)d_in[12];
    const float* b_feat = (const float*)d_in[13];
    const float* W_comb = (const float*)d_in[14];
    const float* b_comb = (const float*)d_in[15];
    const float* W_ih   = (const float*)d_in[16];
    const float* W_hh   = (const float*)d_in[17];
    const float* b_ih   = (const float*)d_in[18];
    const float* b_hh   = (const float*)d_in[19];
    const float* W_anc  = (const float*)d_in[20];
    const float* b_anc  = (const float*)d_in[21];
    const float* W_cat  = (const float*)d_in[22];
    const float* b_cat  = (const float*)d_in[23];
    const float* W_out  = (const float*)d_in[24];
    const float* b_out  = (const float*)d_in[25];
    float* out = (float*)d_out;

    rits_prep<<<64, NTHR>>>(W_ih, W_hh, b_ih, b_hh);
    rits_main<<<NBLK, NTHR>>>(values, masks, deltas, probs, ancillary, labels,
                              W_td_h, b_td_h, W_td_x, b_td_x, W_hist, b_hist,
                              W_feat, b_feat, W_comb, b_comb,
                              W_anc, b_anc, W_cat, b_cat, W_out, b_out, out);
    rits_finalize<<<1, NTHR>>>(out);
}

// round 7
// speedup vs baseline: 1.0052x; 1.0052x over previous
#include <cuda_runtime.h>
#include <cuda_bf16.h>

// ---------------- problem constants ----------------
#define BN 8192
#define TN 223
#define DN 7
#define HN 128
#define EN 50
#define ON 29
#define AN 9
#define KT 142              // gate GEMV depth: 128 h + 7 c_c + 7 m
#define NTHR 256
#define NBLK 512            // 512 blocks * 16 elements = 8192
#define VP 10               // padded pair-dim of sh_v (float2 units)

// output layout (float32): x_loss, y_loss, loss, y_h[B][O], imputations[B][T][D], labels[B]
#define YH_OFF 3
#define IMP_OFF (3 + BN*ON)
#define LBL_OFF (IMP_OFF + BN*TN*DN)

// ---------------- device scratch (static: no allocation) ----------------
__device__ float4 g_W4[KT + 1][HN];   // [k][j] -> (Wi,Wf,Wg,Wo); rows 0-127 W_hh, 128-141 W_ih (+1 pad)
__device__ float4 g_b4[HN];           // combined gate biases per j
__device__ float  g_part[4][TN];      // per-timestep partials: msum, l1, l2, l3
__device__ float  g_yloss;

// ---------------- helpers ----------------
union F2U { float2 f; unsigned long long u; };
__device__ __forceinline__ float2 f2fma(float2 a, float2 b, float2 c) {
    F2U A, B, C, R; A.f = a; B.f = b; C.f = c;
    asm("fma.rn.f32x2 %0, %1, %2, %3;" : "=l"(R.u) : "l"(A.u), "l"(B.u), "l"(C.u));
    return R.f;
}
__device__ __forceinline__ float sig1(float x) { return __fdividef(1.f, 1.f + __expf(-x)); }
__device__ __forceinline__ float th1(float x)  { return 1.f - __fdividef(2.f, __expf(2.f * x) + 1.f); }

__device__ __forceinline__ void fma4(float2* acc, float w,
                                     float2 h0, float2 h1, float2 h2, float2 h3) {
    float2 wb = make_float2(w, w);
    acc[0] = f2fma(wb, h0, acc[0]);
    acc[1] = f2fma(wb, h1, acc[1]);
    acc[2] = f2fma(wb, h2, acc[2]);
    acc[3] = f2fma(wb, h3, acc[3]);
}

// ---------------- prep: pack gate weights, zero scratch ----------------
__global__ void rits_prep(const float* __restrict__ W_ih, const float* __restrict__ W_hh,
                          const float* __restrict__ b_ih, const float* __restrict__ b_hh) {
    int i = blockIdx.x * blockDim.x + threadIdx.x;   // grid covers >= 18176
    if (i < KT * HN) {
        int k = i >> 7, j = i & (HN - 1);
        float4 w;
        if (k < HN) {
            w = make_float4(W_hh[j*HN + k],          W_hh[(HN + j)*HN + k],
                            W_hh[(2*HN + j)*HN + k], W_hh[(3*HN + j)*HN + k]);
        } else {
            int c = k - HN;                      // 0..13 : 0-6 c_c cols, 7-13 m cols
            w = make_float4(W_ih[j*2*DN + c],          W_ih[(HN + j)*2*DN + c],
                            W_ih[(2*HN + j)*2*DN + c], W_ih[(3*HN + j)*2*DN + c]);
        }
        g_W4[k][j] = w;
    }
    if (i < HN) {
        g_b4[i] = make_float4(b_ih[i]        + b_hh[i],
                              b_ih[HN + i]   + b_hh[HN + i],
                              b_ih[2*HN + i] + b_hh[2*HN + i],
                              b_ih[3*HN + i] + b_hh[3*HN + i]);
        g_W4[KT][i] = make_float4(0.f, 0.f, 0.f, 0.f);   // pad row
    }
    if (i < 4 * TN) ((float*)g_part)[i] = 0.f;
    if (i == 0) g_yloss = 0.f;
}

// ---------------- main recurrence + head ----------------
__global__ void __launch_bounds__(NTHR, 4) rits_main(
    const float* __restrict__ values,  const float* __restrict__ masks,
    const float* __restrict__ deltas,  const float* __restrict__ probs,
    const float* __restrict__ ancillary, const int* __restrict__ labels,
    const float* __restrict__ W_td_h,  const float* __restrict__ b_td_h,
    const float* __restrict__ W_td_x,  const float* __restrict__ b_td_x,
    const float* __restrict__ W_hist,  const float* __restrict__ b_hist,
    const float* __restrict__ W_feat,  const float* __restrict__ b_feat,
    const float* __restrict__ W_comb,  const float* __restrict__ b_comb,
    const float* __restrict__ W_anc,   const float* __restrict__ b_anc,
    const float* __restrict__ W_cat,   const float* __restrict__ b_cat,
    const float* __restrict__ W_out,   const float* __restrict__ b_out,
    float* __restrict__ out)
{
    // unified operand buffer: rows 0-127 = h (decayed in place), 128-134 = c_c, 135-141 = m
    __shared__ __align__(16) float2 sh_v[2][KT][VP];
    __shared__ __align__(16) float2 sh_c[8][HN];        // cell state, pair-major
    __shared__ __align__(16) float2 sh_x[2][DN][8], sh_d[2][DN][8], sh_gx[2][DN][8];
    __shared__ __align__(16) float2 sh_xh[DN][8], sh_xc[DN][8];
    __shared__ float sh_wbuf[2*HN*DN];                  // loop: WhT | Wtdh ; head: anc | lg
    __shared__ float sh_btdh[HN];
    __shared__ float sh_Wf[DN*DN], sh_Wcb[DN*2*DN];
    __shared__ float sh_bh[DN], sh_bf[DN], sh_bc[DN], sh_tdx[DN], sh_btdx[DN];
    __shared__ float sh_red[4];

    float* sh_WhT  = sh_wbuf;                           // [j*7+k] = W_hist[k][j]
    float* sh_Wtdh = sh_wbuf + HN*DN;                   // [j*7+k] = W_td_h[j][k]

    const int tid  = threadIdx.x;
    const int j    = tid >> 1;          // hidden unit 0..127
    const int half = tid & 1;           // pairs 4*half .. 4*half+3
    const int eb   = blockIdx.x * 16;

    // ---- init: small weights + t=0 inputs + zero state ----
    for (int i = tid; i < HN*DN; i += NTHR) {
        int jj = i / DN, kk = i - jj * DN;
        sh_WhT[i]  = W_hist[kk * HN + jj];
        sh_Wtdh[i] = W_td_h[i];
    }
    for (int i = tid; i < HN; i += NTHR) sh_btdh[i] = b_td_h[i];
    if (tid < DN*DN) {
        int a = tid / DN, b = tid % DN;
        sh_Wf[tid] = (a == b) ? 0.f : W_feat[tid];
    }
    if (tid < DN*2*DN) sh_Wcb[tid] = W_comb[tid];
    if (tid < DN) {
        sh_bh[tid]   = b_hist[tid];
        sh_bf[tid]   = b_feat[tid];
        sh_bc[tid]   = b_comb[tid];
        sh_tdx[tid]  = W_td_x[tid * DN + tid];
        sh_btdx[tid] = b_td_x[tid];
    }
    for (int i = tid; i < HN*VP; i += NTHR)
        sh_v[0][i / VP][i % VP] = make_float2(0.f, 0.f);    // h0 = 0
    for (int i = tid; i < 8*HN; i += NTHR)
        ((float2*)sh_c)[i] = make_float2(0.f, 0.f);         // c0 = 0
    if (tid < 4) sh_red[tid] = 0.f;
    if (tid < 56) {                                          // t=0 inputs -> buf 0
        int k = tid >> 3, p = tid & 7;
        size_t o0 = (size_t)(eb + 2*p) * TN * DN + k;
        size_t o1 = o0 + (size_t)TN * DN;
        float x0 = values[o0], x1 = values[o1];
        float m0 = masks[o0],  m1 = masks[o1];
        float d0 = deltas[o0], d1 = deltas[o1];
        sh_x[0][k][p] = make_float2(x0, x1);
        sh_d[0][k][p] = make_float2(d0, d1);
        sh_v[0][135+k][p] = make_float2(m0, m1);
        float td = W_td_x[k * DN + k], bx = b_td_x[k];
        sh_gx[0][k][p] = make_float2(__expf(-fmaxf(d0*td + bx, 0.f)),
                                     __expf(-fmaxf(d1*td + bx, 0.f)));
    }

    const float4 b4 = g_b4[j];
    __syncthreads();

    for (int t = 0; t < TN; ++t) {
        const int fb = t & 1, nb = fb ^ 1;

        // ---- Phase B: decay h in place ----
        {
            float bt = sh_btdh[j];
            float2 ga[4];
#pragma unroll
            for (int i = 0; i < 4; i++) ga[i] = make_float2(bt, bt);
#pragma unroll
            for (int kk = 0; kk < DN; kk++) {
                float  wv = sh_Wtdh[j*DN + kk];
                float2 wb = make_float2(wv, wv);
#pragma unroll
                for (int i = 0; i < 4; i++)
                    ga[i] = f2fma(wb, sh_d[fb][kk][4*half + i], ga[i]);
            }
#pragma unroll
            for (int i = 0; i < 4; i++) {
                int p = 4*half + i;
                float2 h2 = sh_v[fb][j][p];
                sh_v[fb][j][p] = make_float2(h2.x * __expf(-fmaxf(ga[i].x, 0.f)),
                                             h2.y * __expf(-fmaxf(ga[i].y, 0.f)));
            }
        }
        __syncthreads();

        // ---- Phase C (224 thr): x_h via 4-way split reduce; warp 7: prefetch t+1 ----
        if (tid < 224) {
            const int g  = tid & 3;
            const int oi = tid >> 2;       // 0..55
            const int ck = oi >> 3, cp = oi & 7;
            float2 a0 = make_float2(0.f, 0.f), a1 = make_float2(0.f, 0.f);
#pragma unroll
            for (int it = 0; it < 32; it += 2) {
                int j0 = it*4 + g, j1 = (it+1)*4 + g;
                float w0 = sh_WhT[j0*DN + ck], w1 = sh_WhT[j1*DN + ck];
                a0 = f2fma(make_float2(w0, w0), sh_v[fb][j0][cp], a0);
                a1 = f2fma(make_float2(w1, w1), sh_v[fb][j1][cp], a1);
            }
            float ax = a0.x + a1.x, ay = a0.y + a1.y;
            ax += __shfl_xor_sync(0xffffffffu, ax, 1);
            ay += __shfl_xor_sync(0xffffffffu, ay, 1);
            ax += __shfl_xor_sync(0xffffffffu, ax, 2);
            ay += __shfl_xor_sync(0xffffffffu, ay, 2);
            if (g == 0) {
                float bhv = sh_bh[ck];
                float2 a = make_float2(ax + bhv, ay + bhv);
                float2 x = sh_x[fb][ck][cp];
                float2 m = sh_v[fb][135+ck][cp];
                sh_xh[ck][cp] = a;
                sh_xc[ck][cp] = make_float2(m.x*x.x + (1.f - m.x)*a.x,
                                            m.y*x.y + (1.f - m.y)*a.y);
                atomicAdd(&sh_red[0], m.x + m.y);
                atomicAdd(&sh_red[1], m.x * fabsf(x.x - a.x) + m.y * fabsf(x.y - a.y));
            }
        } else if (t + 1 < TN) {
            // warp 7 prefetches step t+1 inputs into buffer nb
            for (int s = tid - 224; s < 56; s += 32) {
                int k = s >> 3, p = s & 7;
                size_t o0 = ((size_t)(eb + 2*p) * TN + (t + 1)) * DN + k;
                size_t o1 = o0 + (size_t)TN * DN;
                float x0 = values[o0], x1 = values[o1];
                float m0 = masks[o0],  m1 = masks[o1];
                float d0 = deltas[o0], d1 = deltas[o1];
                sh_x[nb][k][p] = make_float2(x0, x1);
                sh_d[nb][k][p] = make_float2(d0, d1);
                sh_v[nb][135+k][p] = make_float2(m0, m1);
                float td = sh_tdx[k], bx = sh_btdx[k];
                sh_gx[nb][k][p] = make_float2(__expf(-fmaxf(d0*td + bx, 0.f)),
                                              __expf(-fmaxf(d1*td + bx, 0.f)));
            }
        }
        __syncthreads();

        // ---- Phase D (56 thr): z_h, alpha, c_h, c_c, losses, imputation ----
        if (tid < 56) {
            const int sk = tid >> 3, sp = tid & 7;
            float2 x  = sh_x[fb][sk][sp];
            float2 m  = sh_v[fb][135+sk][sp];
            float2 xh = sh_xh[sk][sp];
            float2 z  = make_float2(sh_bf[sk], sh_bf[sk]);
#pragma unroll
            for (int k2 = 0; k2 < DN; k2++) {
                float w = sh_Wf[sk*DN + k2];
                z = f2fma(make_float2(w, w), sh_xc[k2][sp], z);
            }
            float l2 = m.x * fabsf(x.x - z.x) + m.y * fabsf(x.y - z.y);
            float2 al = make_float2(sh_bc[sk], sh_bc[sk]);
#pragma unroll
            for (int k2 = 0; k2 < DN; k2++) {
                float wg = sh_Wcb[sk*2*DN + k2];
                float wm = sh_Wcb[sk*2*DN + DN + k2];
                al = f2fma(make_float2(wg, wg), sh_gx[fb][k2][sp], al);
                al = f2fma(make_float2(wm, wm), sh_v[fb][135+k2][sp], al);
            }
            float2 ch = make_float2(al.x*z.x + (1.f - al.x)*xh.x,
                                    al.y*z.y + (1.f - al.y)*xh.y);
            float l3 = m.x * fabsf(x.x - ch.x) + m.y * fabsf(x.y - ch.y);
            float2 cc = make_float2(m.x*x.x + (1.f - m.x)*ch.x,
                                    m.y*x.y + (1.f - m.y)*ch.y);
            sh_v[fb][128+sk][sp] = cc;
            size_t o0 = ((size_t)(eb + 2*sp) * TN + t) * DN + sk;
            size_t o1 = o0 + (size_t)TN * DN;
            out[IMP_OFF + o0] = cc.x;
            out[IMP_OFF + o1] = cc.y;
            atomicAdd(&sh_red[2], l2);
            atomicAdd(&sh_red[3], l3);
        }
        __syncthreads();

        // ---- Phase E: unified 142-k gate GEMV (FFMA2) + pointwise ----
        if (tid == 0) {
            atomicAdd(&g_part[0][t], sh_red[0]);
            atomicAdd(&g_part[1][t], sh_red[1]);
            atomicAdd(&g_part[2][t], sh_red[2]);
            atomicAdd(&g_part[3][t], sh_red[3]);
            sh_red[0] = 0.f; sh_red[1] = 0.f; sh_red[2] = 0.f; sh_red[3] = 0.f;
        }
        {
            float2 acc[4][4];
#pragma unroll
            for (int i = 0; i < 4; i++) {
                acc[0][i] = make_float2(b4.x, b4.x);
                acc[1][i] = make_float2(b4.y, b4.y);
                acc[2][i] = make_float2(b4.z, b4.z);
                acc[3][i] = make_float2(b4.w, b4.w);
            }
            const float2* vrow = &sh_v[fb][0][4*half];
            const float4* wcol = &g_W4[0][j];
#pragma unroll 1
            for (int k = 0; k < KT; ++k) {
                float4 w  = wcol[(size_t)k * HN];
                float4 va = *(const float4*)(vrow);
                float4 vb = *(const float4*)(vrow + 2);
                vrow += VP;
                float2 h0 = make_float2(va.x, va.y), h1 = make_float2(va.z, va.w);
                float2 h2 = make_float2(vb.x, vb.y), h3 = make_float2(vb.z, vb.w);
                fma4(acc[0], w.x, h0, h1, h2, h3);
                fma4(acc[1], w.y, h0, h1, h2, h3);
                fma4(acc[2], w.z, h0, h1, h2, h3);
                fma4(acc[3], w.w, h0, h1, h2, h3);
            }
            // pointwise LSTM update (c in shared)
            float2 hnew[4];
#pragma unroll
            for (int i = 0; i < 4; i++) {
                float2 cv = sh_c[4*half + i][j];
                float igx = sig1(acc[0][i].x), igy = sig1(acc[0][i].y);
                float fgx = sig1(acc[1][i].x), fgy = sig1(acc[1][i].y);
                float ggx = th1(acc[2][i].x),  ggy = th1(acc[2][i].y);
                float ogx = sig1(acc[3][i].x), ogy = sig1(acc[3][i].y);
                cv = make_float2(fgx * cv.x + igx * ggx,
                                 fgy * cv.y + igy * ggy);
                sh_c[4*half + i][j] = cv;
                hnew[i] = make_float2(ogx * th1(cv.x), ogy * th1(cv.y));
            }
            *(float4*)&sh_v[nb][j][4*half]     = make_float4(hnew[0].x, hnew[0].y, hnew[1].x, hnew[1].y);
            *(float4*)&sh_v[nb][j][4*half + 2] = make_float4(hnew[2].x, hnew[2].y, hnew[3].x, hnew[3].y);
        }
        __syncthreads();
    }

    // ================= head (final h in sh_v[1]; TN odd) =================
    float (*sh_anc)[16] = (float(*)[16])sh_wbuf;           // 50*16 floats
    float (*sh_lg)[16]  = (float(*)[16])(sh_wbuf + EN*16); // 29*16 floats
    float* sh_hc = (float*)&sh_c[0][0];                    // [128][16] floats (8KB)

    for (int u = tid; u < 16 * EN; u += NTHR) {
        int e = u & 15, q = u >> 4;
        const float* ar = ancillary + (size_t)(eb + e) * AN;
        float a = b_anc[q];
#pragma unroll
        for (int k = 0; k < AN; k++) a += ar[k] * W_anc[q*AN + k];
        sh_anc[q][e] = fmaxf(a, 0.f);
    }
    __syncthreads();

    {
        const float* wc = W_cat + (size_t)j * (HN + EN);
        float2 accp[4];
        float  bc = b_cat[j];
#pragma unroll
        for (int i = 0; i < 4; i++) accp[i] = make_float2(bc, bc);
        for (int jj = 0; jj < HN; jj++) {
            float  w  = wc[jj];
            float2 wb = make_float2(w, w);
#pragma unroll
            for (int i = 0; i < 4; i++)
                accp[i] = f2fma(wb, sh_v[1][jj][4*half + i], accp[i]);
        }
        float hcv[8];
#pragma unroll
        for (int i = 0; i < 4; i++) { hcv[2*i] = accp[i].x; hcv[2*i+1] = accp[i].y; }
        for (int q = 0; q < EN; q++) {
            float w = wc[HN + q];
#pragma unroll
            for (int i = 0; i < 8; i++) hcv[i] += w * sh_anc[q][8*half + i];
        }
        __syncthreads();   // sh_c reads (pointwise) done; safe to overwrite as sh_hc
#pragma unroll
        for (int i = 0; i < 8; i++)
            sh_hc[j*16 + 8*half + i] = fmaxf(hcv[i], 0.f);
    }
    __syncthreads();

    for (int u = tid; u < 16 * ON; u += NTHR) {
        int e = u & 15, o = u >> 4;
        const float* wo = W_out + (size_t)o * HN;
        float a = b_out[o];
#pragma unroll 8
        for (int jj = 0; jj < HN; jj++) a += sh_hc[jj*16 + e] * wo[jj];
        sh_lg[o][e] = a;
    }
    __syncthreads();

    if (tid < 16) {
        int e = tid;
        float mx = -1e30f;
        for (int o = 0; o < ON; o++) mx = fmaxf(mx, sh_lg[o][e]);
        float s = 0.f;
        for (int o = 0; o < ON; o++) s += __expf(sh_lg[o][e] - mx);
        float inv = __fdividef(1.f, s);
        const float* pr = probs + (size_t)(eb + e) * ON;
        float* yo = out + YH_OFF + (size_t)(eb + e) * ON;
        float yl = 0.f;
        for (int o = 0; o < ON; o++) {
            float y = __expf(sh_lg[o][e] - mx) * inv;
            yo[o] = y;
            float dd = y - pr[o];
            yl += dd * dd;
        }
        atomicAdd(&g_yloss, yl);
        out[LBL_OFF + eb + e] = (float)labels[eb + e];
    }
}

// ---------------- finalize: assemble scalars ----------------
__global__ void rits_finalize(float* __restrict__ out) {
    __shared__ float s[NTHR];
    int t = threadIdx.x;
    float v = 0.f;
    if (t < TN)
        v = (g_part[1][t] + g_part[2][t] + g_part[3][t]) / (g_part[0][t] + 1e-5f);
    s[t] = v;
    __syncthreads();
    for (int st = NTHR/2; st > 0; st >>= 1) {
        if (t < st) s[t] += s[t + st];
        __syncthreads();
    }
    if (t == 0) {
        float xl = 0.3f * s[0];                    // IMPUTE_W
        float yl = g_yloss / (8192.0f + 1e-5f);    // LABEL_W = 1
        out[0] = xl;
        out[1] = yl;
        out[2] = xl + yl;
    }
}

// ---------------- launcher ----------------
extern "C" void kernel_launch(void* const* d_in, const int* in_sizes, int n_in,
                              void* d_out, int out_size) {
    (void)in_sizes; (void)n_in; (void)out_size;
    const float* values    = (const float*)d_in[0];
    const float* masks     = (const float*)d_in[1];
    const float* deltas    = (const float*)d_in[2];
    const float* probs     = (const float*)d_in[3];
    const float* ancillary = (const float*)d_in[4];
    const int*   labels    = (const int*)  d_in[5];
    const float* W_td_h = (const float*)d_in[6];
    const float* b_td_h = (const float*)d_in[7];
    const float* W_td_x = (const float*)d_in[8];
    const float* b_td_x = (const float*)d_in[9];
    const float* W_hist = (const float*)d_in[10];
    const float* b_hist = (const float*)d_in[11];
    const float* W_feat = (const float*)d_in[12];
    const float* b_feat = (const float*)d_in[13];
    const float* W_comb = (const float*)d_in[14];
    const float* b_comb = (const float*)d_in[15];
    const float* W_ih   = (const float*)d_in[16];
    const float* W_hh   = (const float*)d_in[17];
    const float* b_ih   = (const float*)d_in[18];
    const float* b_hh   = (const float*)d_in[19];
    const float* W_anc  = (const float*)d_in[20];
    const float* b_anc  = (const float*)d_in[21];
    const float* W_cat  = (const float*)d_in[22];
    const float* b_cat  = (const float*)d_in[23];
    const float* W_out  = (const float*)d_in[24];
    const float* b_out  = (const float*)d_in[25];
    float* out = (float*)d_out;

    rits_prep<<<80, NTHR>>>(W_ih, W_hh, b_ih, b_hh);
    rits_main<<<NBLK, NTHR>>>(values, masks, deltas, probs, ancillary, labels,
                              W_td_h, b_td_h, W_td_x, b_td_x, W_hist, b_hist,
                              W_feat, b_feat, W_comb, b_comb,
                              W_anc, b_anc, W_cat, b_cat, W_out, b_out, out);
    rits_finalize<<<1, NTHR>>>(out);
}

// round 8
// speedup vs baseline: 1.0764x; 1.0709x over previous
#include <cuda_runtime.h>
#include <cuda_bf16.h>

// ---------------- problem constants ----------------
#define BN 8192
#define TN 223
#define DN 7
#define HN 128
#define EN 50
#define ON 29
#define AN 9
#define KT 142              // gate GEMV depth: 128 h + 7 c_c + 7 m
#define NTHR 256
#define NBLK 512            // 512 blocks * 16 elements = 8192
#define VP 10               // padded pair-dim of sh_v (float2 units)

// output layout (float32): x_loss, y_loss, loss, y_h[B][O], imputations[B][T][D], labels[B]
#define YH_OFF 3
#define IMP_OFF (3 + BN*ON)
#define LBL_OFF (IMP_OFF + BN*TN*DN)

// ---------------- device scratch (static: no allocation) ----------------
__device__ float4 g_W4[KT + 1][HN];   // [k][j] -> (Wi,Wf,Wg,Wo); rows 0-127 W_hh, 128-141 W_ih (+1 pad)
__device__ float4 g_b4[HN];           // combined gate biases per j
__device__ float  g_part[4][TN];      // per-timestep partials: msum, l1, l2, l3
__device__ float  g_yloss;

// ---------------- helpers ----------------
union F2U { float2 f; unsigned long long u; };
__device__ __forceinline__ float2 f2fma(float2 a, float2 b, float2 c) {
    F2U A, B, C, R; A.f = a; B.f = b; C.f = c;
    asm("fma.rn.f32x2 %0, %1, %2, %3;" : "=l"(R.u) : "l"(A.u), "l"(B.u), "l"(C.u));
    return R.f;
}
__device__ __forceinline__ float sig1(float x) { return __fdividef(1.f, 1.f + __expf(-x)); }
__device__ __forceinline__ float th1(float x)  { return 1.f - __fdividef(2.f, __expf(2.f * x) + 1.f); }

__device__ __forceinline__ void fma4(float2* acc, float w,
                                     float2 h0, float2 h1, float2 h2, float2 h3) {
    float2 wb = make_float2(w, w);
    acc[0] = f2fma(wb, h0, acc[0]);
    acc[1] = f2fma(wb, h1, acc[1]);
    acc[2] = f2fma(wb, h2, acc[2]);
    acc[3] = f2fma(wb, h3, acc[3]);
}

// ---------------- prep: pack gate weights, zero scratch ----------------
__global__ void rits_prep(const float* __restrict__ W_ih, const float* __restrict__ W_hh,
                          const float* __restrict__ b_ih, const float* __restrict__ b_hh) {
    int i = blockIdx.x * blockDim.x + threadIdx.x;   // grid covers >= 18176
    if (i < KT * HN) {
        int k = i >> 7, j = i & (HN - 1);
        float4 w;
        if (k < HN) {
            w = make_float4(W_hh[j*HN + k],          W_hh[(HN + j)*HN + k],
                            W_hh[(2*HN + j)*HN + k], W_hh[(3*HN + j)*HN + k]);
        } else {
            int c = k - HN;                      // 0..13 : 0-6 c_c cols, 7-13 m cols
            w = make_float4(W_ih[j*2*DN + c],          W_ih[(HN + j)*2*DN + c],
                            W_ih[(2*HN + j)*2*DN + c], W_ih[(3*HN + j)*2*DN + c]);
        }
        g_W4[k][j] = w;
    }
    if (i < HN) {
        g_b4[i] = make_float4(b_ih[i]        + b_hh[i],
                              b_ih[HN + i]   + b_hh[HN + i],
                              b_ih[2*HN + i] + b_hh[2*HN + i],
                              b_ih[3*HN + i] + b_hh[3*HN + i]);
        g_W4[KT][i] = make_float4(0.f, 0.f, 0.f, 0.f);   // pad row
    }
    if (i < 4 * TN) ((float*)g_part)[i] = 0.f;
    if (i == 0) g_yloss = 0.f;
}

// ---------------- main recurrence + head ----------------
__global__ void __launch_bounds__(NTHR, 4) rits_main(
    const float* __restrict__ values,  const float* __restrict__ masks,
    const float* __restrict__ deltas,  const float* __restrict__ probs,
    const float* __restrict__ ancillary, const int* __restrict__ labels,
    const float* __restrict__ W_td_h,  const float* __restrict__ b_td_h,
    const float* __restrict__ W_td_x,  const float* __restrict__ b_td_x,
    const float* __restrict__ W_hist,  const float* __restrict__ b_hist,
    const float* __restrict__ W_feat,  const float* __restrict__ b_feat,
    const float* __restrict__ W_comb,  const float* __restrict__ b_comb,
    const float* __restrict__ W_anc,   const float* __restrict__ b_anc,
    const float* __restrict__ W_cat,   const float* __restrict__ b_cat,
    const float* __restrict__ W_out,   const float* __restrict__ b_out,
    float* __restrict__ out)
{
    // unified operand buffer: rows 0-127 = h (decayed in place), 128-134 = c_c, 135-141 = m
    __shared__ __align__(16) float2 sh_v[2][KT][VP];
    __shared__ __align__(16) float2 sh_c[8][HN];        // cell state, pair-major
    __shared__ __align__(16) float2 sh_x[2][DN][8], sh_d[2][DN][8], sh_gx[2][DN][8];
    __shared__ __align__(16) float2 sh_xh[DN][8], sh_xc[DN][8];
    __shared__ float sh_wbuf[2*HN*DN];                  // loop: WhT | Wtdh ; head: anc | lg
    __shared__ float sh_btdh[HN];
    __shared__ float sh_Wf[DN*DN], sh_Wcb[DN*2*DN];
    __shared__ float sh_bh[DN], sh_bf[DN], sh_bc[DN], sh_tdx[DN], sh_btdx[DN];
    __shared__ float sh_red[4];

    float* sh_WhT  = sh_wbuf;                           // [j*7+k] = W_hist[k][j]
    float* sh_Wtdh = sh_wbuf + HN*DN;                   // [j*7+k] = W_td_h[j][k]

    const int tid  = threadIdx.x;
    const int j    = tid >> 1;          // hidden unit 0..127
    const int half = tid & 1;           // pairs 4*half .. 4*half+3
    const int eb   = blockIdx.x * 16;

    // ---- init: small weights + t=0 inputs + zero state ----
    for (int i = tid; i < HN*DN; i += NTHR) {
        int jj = i / DN, kk = i - jj * DN;
        sh_WhT[i]  = W_hist[kk * HN + jj];
        sh_Wtdh[i] = W_td_h[i];
    }
    for (int i = tid; i < HN; i += NTHR) sh_btdh[i] = b_td_h[i];
    if (tid < DN*DN) {
        int a = tid / DN, b = tid % DN;
        sh_Wf[tid] = (a == b) ? 0.f : W_feat[tid];
    }
    if (tid < DN*2*DN) sh_Wcb[tid] = W_comb[tid];
    if (tid < DN) {
        sh_bh[tid]   = b_hist[tid];
        sh_bf[tid]   = b_feat[tid];
        sh_bc[tid]   = b_comb[tid];
        sh_tdx[tid]  = W_td_x[tid * DN + tid];
        sh_btdx[tid] = b_td_x[tid];
    }
    for (int i = tid; i < HN*VP; i += NTHR)
        sh_v[0][i / VP][i % VP] = make_float2(0.f, 0.f);    // h0 = 0
    for (int i = tid; i < 8*HN; i += NTHR)
        ((float2*)sh_c)[i] = make_float2(0.f, 0.f);         // c0 = 0
    if (tid < 4) sh_red[tid] = 0.f;
    if (tid < 56) {                                          // t=0 inputs -> buf 0
        int k = tid >> 3, p = tid & 7;
        size_t o0 = (size_t)(eb + 2*p) * TN * DN + k;
        size_t o1 = o0 + (size_t)TN * DN;
        float x0 = values[o0], x1 = values[o1];
        float m0 = masks[o0],  m1 = masks[o1];
        float d0 = deltas[o0], d1 = deltas[o1];
        sh_x[0][k][p] = make_float2(x0, x1);
        sh_d[0][k][p] = make_float2(d0, d1);
        sh_v[0][135+k][p] = make_float2(m0, m1);
        float td = W_td_x[k * DN + k], bx = b_td_x[k];
        sh_gx[0][k][p] = make_float2(__expf(-fmaxf(d0*td + bx, 0.f)),
                                     __expf(-fmaxf(d1*td + bx, 0.f)));
    }

    const float4 b4 = g_b4[j];
    __syncthreads();

    for (int t = 0; t < TN; ++t) {
        const int fb = t & 1, nb = fb ^ 1;

        // ---- Phase B: decay h in place ----
        {
            float bt = sh_btdh[j];
            float2 ga[4];
#pragma unroll
            for (int i = 0; i < 4; i++) ga[i] = make_float2(bt, bt);
#pragma unroll
            for (int kk = 0; kk < DN; kk++) {
                float  wv = sh_Wtdh[j*DN + kk];
                float2 wb = make_float2(wv, wv);
#pragma unroll
                for (int i = 0; i < 4; i++)
                    ga[i] = f2fma(wb, sh_d[fb][kk][4*half + i], ga[i]);
            }
#pragma unroll
            for (int i = 0; i < 4; i++) {
                int p = 4*half + i;
                float2 h2 = sh_v[fb][j][p];
                sh_v[fb][j][p] = make_float2(h2.x * __expf(-fmaxf(ga[i].x, 0.f)),
                                             h2.y * __expf(-fmaxf(ga[i].y, 0.f)));
            }
        }
        __syncthreads();

        // ---- Phase C (224 thr): x_h via 4-way split reduce; warp 7: prefetch t+1 ----
        if (tid < 224) {
            const int g  = tid & 3;
            const int oi = tid >> 2;       // 0..55
            const int ck = oi >> 3, cp = oi & 7;
            float2 a0 = make_float2(0.f, 0.f), a1 = make_float2(0.f, 0.f);
#pragma unroll
            for (int it = 0; it < 32; it += 2) {
                int j0 = it*4 + g, j1 = (it+1)*4 + g;
                float w0 = sh_WhT[j0*DN + ck], w1 = sh_WhT[j1*DN + ck];
                a0 = f2fma(make_float2(w0, w0), sh_v[fb][j0][cp], a0);
                a1 = f2fma(make_float2(w1, w1), sh_v[fb][j1][cp], a1);
            }
            float ax = a0.x + a1.x, ay = a0.y + a1.y;
            ax += __shfl_xor_sync(0xffffffffu, ax, 1);
            ay += __shfl_xor_sync(0xffffffffu, ay, 1);
            ax += __shfl_xor_sync(0xffffffffu, ax, 2);
            ay += __shfl_xor_sync(0xffffffffu, ay, 2);
            if (g == 0) {
                float bhv = sh_bh[ck];
                float2 a = make_float2(ax + bhv, ay + bhv);
                float2 x = sh_x[fb][ck][cp];
                float2 m = sh_v[fb][135+ck][cp];
                sh_xh[ck][cp] = a;
                sh_xc[ck][cp] = make_float2(m.x*x.x + (1.f - m.x)*a.x,
                                            m.y*x.y + (1.f - m.y)*a.y);
                atomicAdd(&sh_red[0], m.x + m.y);
                atomicAdd(&sh_red[1], m.x * fabsf(x.x - a.x) + m.y * fabsf(x.y - a.y));
            }
        } else if (t + 1 < TN) {
            // warp 7 prefetches step t+1 inputs into buffer nb
            for (int s = tid - 224; s < 56; s += 32) {
                int k = s >> 3, p = s & 7;
                size_t o0 = ((size_t)(eb + 2*p) * TN + (t + 1)) * DN + k;
                size_t o1 = o0 + (size_t)TN * DN;
                float x0 = values[o0], x1 = values[o1];
                float m0 = masks[o0],  m1 = masks[o1];
                float d0 = deltas[o0], d1 = deltas[o1];
                sh_x[nb][k][p] = make_float2(x0, x1);
                sh_d[nb][k][p] = make_float2(d0, d1);
                sh_v[nb][135+k][p] = make_float2(m0, m1);
                float td = sh_tdx[k], bx = sh_btdx[k];
                sh_gx[nb][k][p] = make_float2(__expf(-fmaxf(d0*td + bx, 0.f)),
                                              __expf(-fmaxf(d1*td + bx, 0.f)));
            }
        }
        __syncthreads();

        // ---- Phase D (56 thr): z_h, alpha, c_h, c_c, losses, imputation ----
        if (tid < 56) {
            const int sk = tid >> 3, sp = tid & 7;
            float2 x  = sh_x[fb][sk][sp];
            float2 m  = sh_v[fb][135+sk][sp];
            float2 xh = sh_xh[sk][sp];
            float2 z  = make_float2(sh_bf[sk], sh_bf[sk]);
#pragma unroll
            for (int k2 = 0; k2 < DN; k2++) {
                float w = sh_Wf[sk*DN + k2];
                z = f2fma(make_float2(w, w), sh_xc[k2][sp], z);
            }
            float l2 = m.x * fabsf(x.x - z.x) + m.y * fabsf(x.y - z.y);
            float2 al = make_float2(sh_bc[sk], sh_bc[sk]);
#pragma unroll
            for (int k2 = 0; k2 < DN; k2++) {
                float wg = sh_Wcb[sk*2*DN + k2];
                float wm = sh_Wcb[sk*2*DN + DN + k2];
                al = f2fma(make_float2(wg, wg), sh_gx[fb][k2][sp], al);
                al = f2fma(make_float2(wm, wm), sh_v[fb][135+k2][sp], al);
            }
            float2 ch = make_float2(al.x*z.x + (1.f - al.x)*xh.x,
                                    al.y*z.y + (1.f - al.y)*xh.y);
            float l3 = m.x * fabsf(x.x - ch.x) + m.y * fabsf(x.y - ch.y);
            float2 cc = make_float2(m.x*x.x + (1.f - m.x)*ch.x,
                                    m.y*x.y + (1.f - m.y)*ch.y);
            sh_v[fb][128+sk][sp] = cc;
            size_t o0 = ((size_t)(eb + 2*sp) * TN + t) * DN + sk;
            size_t o1 = o0 + (size_t)TN * DN;
            out[IMP_OFF + o0] = cc.x;
            out[IMP_OFF + o1] = cc.y;
            atomicAdd(&sh_red[2], l2);
            atomicAdd(&sh_red[3], l3);
        }
        __syncthreads();

        // ---- Phase E: unified 142-k gate GEMV (FFMA2) + pointwise ----
        if (tid == 0) {
            atomicAdd(&g_part[0][t], sh_red[0]);
            atomicAdd(&g_part[1][t], sh_red[1]);
            atomicAdd(&g_part[2][t], sh_red[2]);
            atomicAdd(&g_part[3][t], sh_red[3]);
            sh_red[0] = 0.f; sh_red[1] = 0.f; sh_red[2] = 0.f; sh_red[3] = 0.f;
        }
        {
            float2 acc[4][4];
#pragma unroll
            for (int i = 0; i < 4; i++) {
                acc[0][i] = make_float2(b4.x, b4.x);
                acc[1][i] = make_float2(b4.y, b4.y);
                acc[2][i] = make_float2(b4.z, b4.z);
                acc[3][i] = make_float2(b4.w, b4.w);
            }
            const float2* vrow = &sh_v[fb][0][4*half];
            const float4* wcol = &g_W4[0][j];
#pragma unroll 1
            for (int k = 0; k < KT; ++k) {
                float4 w  = wcol[(size_t)k * HN];
                float4 va = *(const float4*)(vrow);
                float4 vb = *(const float4*)(vrow + 2);
                vrow += VP;
                float2 h0 = make_float2(va.x, va.y), h1 = make_float2(va.z, va.w);
                float2 h2 = make_float2(vb.x, vb.y), h3 = make_float2(vb.z, vb.w);
                fma4(acc[0], w.x, h0, h1, h2, h3);
                fma4(acc[1], w.y, h0, h1, h2, h3);
                fma4(acc[2], w.z, h0, h1, h2, h3);
                fma4(acc[3], w.w, h0, h1, h2, h3);
            }
            // pointwise LSTM update (c in shared)
            float2 hnew[4];
#pragma unroll
            for (int i = 0; i < 4; i++) {
                float2 cv = sh_c[4*half + i][j];
                float igx = sig1(acc[0][i].x), igy = sig1(acc[0][i].y);
                float fgx = sig1(acc[1][i].x), fgy = sig1(acc[1][i].y);
                float ggx = th1(acc[2][i].x),  ggy = th1(acc[2][i].y);
                float ogx = sig1(acc[3][i].x), ogy = sig1(acc[3][i].y);
                cv = make_float2(fgx * cv.x + igx * ggx,
                                 fgy * cv.y + igy * ggy);
                sh_c[4*half + i][j] = cv;
                hnew[i] = make_float2(ogx * th1(cv.x), ogy * th1(cv.y));
            }
            *(float4*)&sh_v[nb][j][4*half]     = make_float4(hnew[0].x, hnew[0].y, hnew[1].x, hnew[1].y);
            *(float4*)&sh_v[nb][j][4*half + 2] = make_float4(hnew[2].x, hnew[2].y, hnew[3].x, hnew[3].y);
        }
        __syncthreads();
    }

    // ================= head (final h in sh_v[1]; TN odd) =================
    float (*sh_anc)[16] = (float(*)[16])sh_wbuf;           // 50*16 floats
    float (*sh_lg)[16]  = (float(*)[16])(sh_wbuf + EN*16); // 29*16 floats
    float* sh_hc = (float*)&sh_c[0][0];                    // [128][16] floats (8KB)

    for (int u = tid; u < 16 * EN; u += NTHR) {
        int e = u & 15, q = u >> 4;
        const float* ar = ancillary + (size_t)(eb + e) * AN;
        float a = b_anc[q];
#pragma unroll
        for (int k = 0; k < AN; k++) a += ar[k] * W_anc[q*AN + k];
        sh_anc[q][e] = fmaxf(a, 0.f);
    }
    __syncthreads();

    {
        const float* wc = W_cat + (size_t)j * (HN + EN);
        float2 accp[4];
        float  bc = b_cat[j];
#pragma unroll
        for (int i = 0; i < 4; i++) accp[i] = make_float2(bc, bc);
        for (int jj = 0; jj < HN; jj++) {
            float  w  = wc[jj];
            float2 wb = make_float2(w, w);
#pragma unroll
            for (int i = 0; i < 4; i++)
                accp[i] = f2fma(wb, sh_v[1][jj][4*half + i], accp[i]);
        }
        float hcv[8];
#pragma unroll
        for (int i = 0; i < 4; i++) { hcv[2*i] = accp[i].x; hcv[2*i+1] = accp[i].y; }
        for (int q = 0; q < EN; q++) {
            float w = wc[HN + q];
#pragma unroll
            for (int i = 0; i < 8; i++) hcv[i] += w * sh_anc[q][8*half + i];
        }
        __syncthreads();   // sh_c reads (pointwise) done; safe to overwrite as sh_hc
#pragma unroll
        for (int i = 0; i < 8; i++)
            sh_hc[j*16 + 8*half + i] = fmaxf(hcv[i], 0.f);
    }
    __syncthreads();

    for (int u = tid; u < 16 * ON; u += NTHR) {
        int e = u & 15, o = u >> 4;
        const float* wo = W_out + (size_t)o * HN;
        float a = b_out[o];
#pragma unroll 8
        for (int jj = 0; jj < HN; jj++) a += sh_hc[jj*16 + e] * wo[jj];
        sh_lg[o][e] = a;
    }
    __syncthreads();

    if (tid < 16) {
        int e = tid;
        float mx = -1e30f;
        for (int o = 0; o < ON; o++) mx = fmaxf(mx, sh_lg[o][e]);
        float s = 0.f;
        for (int o = 0; o < ON; o++) s += __expf(sh_lg[o][e] - mx);
        float inv = __fdividef(1.f, s);
        const float* pr = probs + (size_t)(eb + e) * ON;
        float* yo = out + YH_OFF + (size_t)(eb + e) * ON;
        float yl = 0.f;
        for (int o = 0; o < ON; o++) {
            float y = __expf(sh_lg[o][e] - mx) * inv;
            yo[o] = y;
            float dd = y - pr[o];
            yl += dd * dd;
        }
        atomicAdd(&g_yloss, yl);
        out[LBL_OFF + eb + e] = (float)labels[eb + e];
    }
}

// ---------------- finalize: assemble scalars ----------------
__global__ void rits_finalize(float* __restrict__ out) {
    __shared__ float s[NTHR];
    int t = threadIdx.x;
    float v = 0.f;
    if (t < TN)
        v = (g_part[1][t] + g_part[2][t] + g_part[3][t]) / (g_part[0][t] + 1e-5f);
    s[t] = v;
    __syncthreads();
    for (int st = NTHR/2; st > 0; st >>= 1) {
        if (t < st) s[t] += s[t + st];
        __syncthreads();
    }
    if (t == 0) {
        float xl = 0.3f * s[0];                    // IMPUTE_W
        float yl = g_yloss / (8192.0f + 1e-5f);    // LABEL_W = 1
        out[0] = xl;
        out[1] = yl;
        out[2] = xl + yl;
    }
}

// ---------------- launcher ----------------
extern "C" void kernel_launch(void* const* d_in, const int* in_sizes, int n_in,
                              void* d_out, int out_size) {
    (void)in_sizes; (void)n_in; (void)out_size;
    const float* values    = (const float*)d_in[0];
    const float* masks     = (const float*)d_in[1];
    const float* deltas    = (const float*)d_in[2];
    const float* probs     = (const float*)d_in[3];
    const float* ancillary = (const float*)d_in[4];
    const int*   labels    = (const int*)  d_in[5];
    const float* W_td_h = (const float*)d_in[6];
    const float* b_td_h = (const float*)d_in[7];
    const float* W_td_x = (const float*)d_in[8];
    const float* b_td_x = (const float*)d_in[9];
    const float* W_hist = (const float*)d_in[10];
    const float* b_hist = (const float*)d_in[11];
    const float* W_feat = (const float*)d_in[12];
    const float* b_feat = (const float*)d_in[13];
    const float* W_comb = (const float*)d_in[14];
    const float* b_comb = (const float*)d_in[15];
    const float* W_ih   = (const float*)d_in[16];
    const float* W_hh   = (const float*)d_in[17];
    const float* b_ih   = (const float*)d_in[18];
    const float* b_hh   = (const float*)d_in[19];
    const float* W_anc  = (const float*)d_in[20];
    const float* b_anc  = (const float*)d_in[21];
    const float* W_cat  = (const float*)d_in[22];
    const float* b_cat  = (const float*)d_in[23];
    const float* W_out  = (const float*)d_in[24];
    const float* b_out  = (const float*)d_in[25];
    float* out = (float*)d_out;

    rits_prep<<<80, NTHR>>>(W_ih, W_hh, b_ih, b_hh);
    rits_main<<<NBLK, NTHR>>>(values, masks, deltas, probs, ancillary, labels,
                              W_td_h, b_td_h, W_td_x, b_td_x, W_hist, b_hist,
                              W_feat, b_feat, W_comb, b_comb,
                              W_anc, b_anc, W_cat, b_cat, W_out, b_out, out);
    rits_finalize<<<1, NTHR>>>(out);
}

// round 13
// speedup vs baseline: 1.7225x; 1.6002x over previous
#include <cuda_runtime.h>
#include <cuda_fp16.h>
#include <cstdint>

#define BN 8192
#define TN 223
#define DN 7
#define HN 128
#define EN 50
#define ON 29
#define AN 9
#define NTHR 256
#define NBLK 128
#define NE 64

#define YH_OFF 3
#define IMP_OFF (3 + BN*ON)
#define LBL_OFF (IMP_OFF + BN*TN*DN)

#define STW 136
#define STE 24
#define STV 152
#define OFF_WH 0
#define OFF_WE 139264
#define OFF_VH 163840
#define OFF_VL 183296
#define OFF_F  202752
#define FXD 0
#define FMD 896
#define FDD 1792
#define FXH 2688
#define FXC 3136
#define FGX 3584
#define FWF 4032
#define FWCB 4081
#define FBH 4179
#define FBF 4186
#define FBC 4193
#define FTDX 4200
#define FBTDX 4207
#define FWHT 4216
#define FRED 5240
#define NFLT 5244
#define SMEM_TOTAL (OFF_F + NFLT*4)

__device__ __align__(16) unsigned char g_wimg[163840];
__device__ float4 g_b4[HN];
__device__ float  g_part[4][TN];
__device__ float  g_yloss;

__device__ __forceinline__ uint32_t smem_u32(const void* p) {
    uint32_t a;
    asm("{ .reg .u64 t; cvta.to.shared.u64 t, %1; cvt.u32.u64 %0, t; }" : "=r"(a) : "l"(p));
    return a;
}
__device__ __forceinline__ void ldsm4(uint32_t& a0, uint32_t& a1, uint32_t& a2, uint32_t& a3, uint32_t ad) {
    asm volatile("ldmatrix.sync.aligned.m8n8.x4.shared.b16 {%0,%1,%2,%3}, [%4];"
                 : "=r"(a0), "=r"(a1), "=r"(a2), "=r"(a3) : "r"(ad));
}
__device__ __forceinline__ void ldsm2(uint32_t& b0, uint32_t& b1, uint32_t ad) {
    asm volatile("ldmatrix.sync.aligned.m8n8.x2.shared.b16 {%0,%1}, [%2];"
                 : "=r"(b0), "=r"(b1) : "r"(ad));
}
__device__ __forceinline__ void mmaop(float* d, uint32_t a0, uint32_t a1, uint32_t a2, uint32_t a3,
                                      uint32_t b0, uint32_t b1) {
    asm volatile("mma.sync.aligned.m16n8k16.row.col.f32.f16.f16.f32 "
                 "{%0,%1,%2,%3}, {%4,%5,%6,%7}, {%8,%9}, {%0,%1,%2,%3};"
                 : "+f"(d[0]), "+f"(d[1]), "+f"(d[2]), "+f"(d[3])
                 : "r"(a0), "r"(a1), "r"(a2), "r"(a3), "r"(b0), "r"(b1));
}
__device__ __forceinline__ float tanhfast(float x) {
    float r; asm("tanh.approx.f32 %0, %1;" : "=f"(r) : "f"(x)); return r;
}
__device__ __forceinline__ float sigf(float x) { return fmaf(tanhfast(0.5f * x), 0.5f, 0.5f); }

__global__ void rits_prep(const float* __restrict__ Wih, const float* __restrict__ Whh,
                          const float* __restrict__ bih, const float* __restrict__ bhh) {
    int i = blockIdx.x * blockDim.x + threadIdx.x;
    if (i < 512 * STW) {
        int r = i / STW, k = i - r * STW;
        ((__half*)g_wimg)[i] = __float2half((k < HN) ? Whh[r * HN + k] : 0.f);
    }
    if (i < 512 * STE) {
        int r = i / STE, c = i - r * STE;
        ((__half*)(g_wimg + OFF_WE))[i] = __float2half((c < 2 * DN) ? Wih[r * 2 * DN + c] : 0.f);
    }
    if (i < HN)
        g_b4[i] = make_float4(bih[i] + bhh[i], bih[HN + i] + bhh[HN + i],
                              bih[2*HN + i] + bhh[2*HN + i], bih[3*HN + i] + bhh[3*HN + i]);
    if (i < 4 * TN) ((float*)g_part)[i] = 0.f;
    if (i == 0) g_yloss = 0.f;
}

__global__ void __launch_bounds__(NTHR) rits_main(
    const float* __restrict__ values,  const float* __restrict__ masks,
    const float* __restrict__ deltas,  const float* __restrict__ probs,
    const float* __restrict__ ancillary, const int* __restrict__ labels,
    const float* __restrict__ W_td_h,  const float* __restrict__ b_td_h,
    const float* __restrict__ W_td_x,  const float* __restrict__ b_td_x,
    const float* __restrict__ W_hist,  const float* __restrict__ b_hist,
    const float* __restrict__ W_feat,  const float* __restrict__ b_feat,
    const float* __restrict__ W_comb,  const float* __restrict__ b_comb,
    const float* __restrict__ W_anc,   const float* __restrict__ b_anc,
    const float* __restrict__ W_cat,   const float* __restrict__ b_cat,
    const float* __restrict__ W_out,   const float* __restrict__ b_out,
    float* __restrict__ out)
{
    extern __shared__ __align__(16) unsigned char sm[];
    float* F = (float*)(sm + OFF_F);
    const uint32_t sb = smem_u32(sm);
    const int tid = threadIdx.x, lane = tid & 31, w = tid >> 5;
    const int gid = lane >> 2, tig = lane & 3;
    const int jb = 16 * w, eb = blockIdx.x * NE;

    for (int i = tid; i < 163840/16; i += NTHR) ((uint4*)sm)[i] = ((const uint4*)g_wimg)[i];
    for (int i = tid; i < 38912/16; i += NTHR) ((uint4*)(sm + OFF_VH))[i] = make_uint4(0,0,0,0);
    if (tid < 49) { int a = tid/7, b = tid%7; F[FWF+tid] = (a==b) ? 0.f : W_feat[tid]; }
    if (tid >= 64 && tid < 162) F[FWCB + tid - 64] = W_comb[tid - 64];
    if (tid >= 192 && tid < 199) {
        int k = tid - 192;
        F[FBH+k] = b_hist[k]; F[FBF+k] = b_feat[k]; F[FBC+k] = b_comb[k];
        F[FTDX+k] = W_td_x[k*DN+k]; F[FBTDX+k] = b_td_x[k];
    }
    if (tid >= 224 && tid < 228) F[FRED + tid - 224] = 0.f;
    for (int i = tid; i < 1024; i += NTHR) {
        int j = i >> 3, k = i & 7;
        F[FWHT + i] = (k < DN) ? W_hist[k * HN + j] : 0.f;
    }
    for (int it = tid; it < 448; it += NTHR) {
        int k = it >> 6, e = it & 63;
        size_t o = (size_t)(eb + e) * TN * DN + k;
        F[FXD+it] = values[o]; F[FMD+it] = masks[o]; F[FDD+it] = deltas[o];
    }

    const int j1 = jb + gid, j2 = j1 + 8;
    float wtdA[DN], wtdB[DN];
#pragma unroll
    for (int k = 0; k < DN; k++) { wtdA[k] = W_td_h[j1*DN+k]; wtdB[k] = W_td_h[j2*DN+k]; }
    const float btdA = b_td_h[j1], btdB = b_td_h[j2];
    const float4 b4a = g_b4[j1], b4b = g_b4[j2];

    uint32_t aW[4], aEx[4];
#pragma unroll
    for (int g = 0; g < 4; g++) {
        aW[g]  = sb + OFF_WH + (uint32_t)((g*128 + jb) + (lane & 15)) * (2*STW) + (lane >> 4) * 16;
        aEx[g] = sb + OFF_WE + (uint32_t)((g*128 + jb) + (lane & 15)) * (2*STE) + (lane >> 4) * 16;
    }
    const uint32_t aVh = sb + OFF_VH + (uint32_t)(lane & 7) * (2*STV) + ((lane >> 3) & 1) * 16;
    const uint32_t aVl = sb + OFF_VL + (uint32_t)(lane & 7) * (2*STV) + ((lane >> 3) & 1) * 16;

    float cst[32];
#pragma unroll
    for (int i = 0; i < 32; i++) cst[i] = 0.f;
    __syncthreads();

    for (int t = 0; t < TN; ++t) {
        const int cur = t & 1, alt = cur ^ 1;

        // ---- x_h scalar (h = hi+lo) ----
        {
            int e = tid >> 2, q = tid & 3, j0 = q * 32;
            const __half* vh = (const __half*)(sm + OFF_VH) + e * STV + j0;
            const __half* vl = (const __half*)(sm + OFF_VL) + e * STV + j0;
            float a[DN] = {0.f, 0.f, 0.f, 0.f, 0.f, 0.f, 0.f};
#pragma unroll
            for (int bq = 0; bq < 4; bq++) {
                uint4 uh = *(const uint4*)(vh + bq * 8);
                uint4 ul = *(const uint4*)(vl + bq * 8);
                const uint32_t* ph = (const uint32_t*)&uh;
                const uint32_t* pl = (const uint32_t*)&ul;
#pragma unroll
                for (int p2 = 0; p2 < 4; p2++) {
                    float2 fh = __half22float2(*(const __half2*)&ph[p2]);
                    float2 fl = __half22float2(*(const __half2*)&pl[p2]);
                    float h0 = fh.x + fl.x, h1 = fh.y + fl.y;
                    const float* w0 = F + FWHT + (j0 + bq*8 + p2*2) * 8;
#pragma unroll
                    for (int k = 0; k < DN; k++)
                        a[k] = fmaf(w0[k], h0, fmaf(w0[8 + k], h1, a[k]));
                }
            }
#pragma unroll
            for (int k = 0; k < DN; k++) {
                a[k] += __shfl_xor_sync(0xffffffffu, a[k], 1);
                a[k] += __shfl_xor_sync(0xffffffffu, a[k], 2);
            }
            if (q == 0) {
#pragma unroll
                for (int k = 0; k < DN; k++) F[FXH + k*64 + e] = a[k] + F[FBH + k];
            }
        }
        __syncthreads();

        // ---- D1: x_c, gamma_x, l0, l1 ----
        float l0 = 0.f, l1 = 0.f;
        for (int it = tid; it < 448; it += NTHR) {
            int k = it >> 6;
            float x = F[FXD + cur*448 + it], m = F[FMD + cur*448 + it], d = F[FDD + cur*448 + it];
            float xh = F[FXH + it];
            F[FXC + it] = m * x + (1.f - m) * xh;
            F[FGX + it] = __expf(-fmaxf(d * F[FTDX + k] + F[FBTDX + k], 0.f));
            l0 += m; l1 += m * fabsf(x - xh);
        }
#pragma unroll
        for (int o = 16; o > 0; o >>= 1) {
            l0 += __shfl_down_sync(0xffffffffu, l0, o);
            l1 += __shfl_down_sync(0xffffffffu, l1, o);
        }
        if (lane == 0) { atomicAdd(&F[FRED], l0); atomicAdd(&F[FRED+1], l1); }
        __syncthreads();

        // ---- D2: z, alpha, c_h, c_c, losses, imputation, V extra; prefetch ----
        float l2 = 0.f, l3 = 0.f;
        for (int it = tid; it < 448; it += NTHR) {
            int k = it >> 6, e = it & 63;
            float x = F[FXD + cur*448 + it], m = F[FMD + cur*448 + it];
            float xh = F[FXH + it];
            float z = F[FBF + k];
#pragma unroll
            for (int k2 = 0; k2 < DN; k2++) z = fmaf(F[FWF + k*7 + k2], F[FXC + k2*64 + e], z);
            l2 += m * fabsf(x - z);
            float al = F[FBC + k];
#pragma unroll
            for (int k2 = 0; k2 < DN; k2++) {
                al = fmaf(F[FWCB + k*14 + k2], F[FGX + k2*64 + e], al);
                al = fmaf(F[FWCB + k*14 + 7 + k2], F[FMD + cur*448 + k2*64 + e], al);
            }
            float ch = al * z + (1.f - al) * xh;
            l3 += m * fabsf(x - ch);
            float cc = m * x + (1.f - m) * ch;
            out[IMP_OFF + ((size_t)(eb + e) * TN + t) * DN + k] = cc;
            *((__half*)(sm + OFF_VH) + e * STV + 128 + k) = __float2half(cc);
            *((__half*)(sm + OFF_VH) + e * STV + 135 + k) = __float2half(m);
        }
        if (t + 1 < TN) {
            for (int it = tid; it < 448; it += NTHR) {
                int k = it >> 6, e = it & 63;
                size_t o = ((size_t)(eb + e) * TN + (t + 1)) * DN + k;
                F[FXD + alt*448 + it] = values[o];
                F[FMD + alt*448 + it] = masks[o];
                F[FDD + alt*448 + it] = deltas[o];
            }
        }
#pragma unroll
        for (int o = 16; o > 0; o >>= 1) {
            l2 += __shfl_down_sync(0xffffffffu, l2, o);
            l3 += __shfl_down_sync(0xffffffffu, l3, o);
        }
        if (lane == 0) { atomicAdd(&F[FRED+2], l2); atomicAdd(&F[FRED+3], l3); }
        __syncthreads();

        if (tid == 0) {
            atomicAdd(&g_part[0][t], F[FRED]);   F[FRED] = 0.f;
            atomicAdd(&g_part[1][t], F[FRED+1]); F[FRED+1] = 0.f;
            atomicAdd(&g_part[2][t], F[FRED+2]); F[FRED+2] = 0.f;
            atomicAdd(&g_part[3][t], F[FRED+3]); F[FRED+3] = 0.f;
        }

        // ---- MMA + epilogue in two n-halves ----
#pragma unroll 1
        for (int nh = 0; nh < 2; nh++) {
            float acc[4][4][4];
#pragma unroll
            for (int g = 0; g < 4; g++)
#pragma unroll
                for (int n2 = 0; n2 < 4; n2++)
#pragma unroll
                    for (int i = 0; i < 4; i++) acc[g][n2][i] = 0.f;
#pragma unroll 1
            for (int kc = 0; kc < 8; kc++) {
                uint32_t A0[4], A1[4], A2[4], A3[4];
#pragma unroll
                for (int g = 0; g < 4; g++) ldsm4(A0[g], A1[g], A2[g], A3[g], aW[g] + kc * 32);
#pragma unroll
                for (int n2 = 0; n2 < 4; n2++) {
                    uint32_t boff = (uint32_t)(nh*4 + n2) * (16*STV) + kc * 32;
                    uint32_t b0, b1;
                    ldsm2(b0, b1, aVh + boff);
#pragma unroll
                    for (int g = 0; g < 4; g++) mmaop(acc[g][n2], A0[g], A1[g], A2[g], A3[g], b0, b1);
                    ldsm2(b0, b1, aVl + boff);
#pragma unroll
                    for (int g = 0; g < 4; g++) mmaop(acc[g][n2], A0[g], A1[g], A2[g], A3[g], b0, b1);
                }
            }
            {
                uint32_t A0[4], A1[4], A2[4], A3[4];
#pragma unroll
                for (int g = 0; g < 4; g++) ldsm4(A0[g], A1[g], A2[g], A3[g], aEx[g]);
#pragma unroll
                for (int n2 = 0; n2 < 4; n2++) {
                    uint32_t b0, b1;
                    ldsm2(b0, b1, aVh + (uint32_t)(nh*4 + n2) * (16*STV) + 256);
#pragma unroll
                    for (int g = 0; g < 4; g++) mmaop(acc[g][n2], A0[g], A1[g], A2[g], A3[g], b0, b1);
                }
            }
            __syncthreads();
#pragma unroll
            for (int n2 = 0; n2 < 4; n2++) {
#pragma unroll
                for (int ee = 0; ee < 2; ee++) {
                    int e = (nh*4 + n2) * 8 + 2*tig + ee;
                    float gaA = 1.f, gaB = 1.f;
                    if (t + 1 < TN) {
                        float sA = btdA, sB = btdB;
#pragma unroll
                        for (int k = 0; k < DN; k++) {
                            float dv = F[FDD + alt*448 + k*64 + e];
                            sA = fmaf(wtdA[k], dv, sA);
                            sB = fmaf(wtdB[k], dv, sB);
                        }
                        gaA = __expf(-fmaxf(sA, 0.f));
                        gaB = __expf(-fmaxf(sB, 0.f));
                    }
#pragma unroll
                    for (int jj = 0; jj < 2; jj++) {
                        const float4 bv = jj ? b4b : b4a;
                        int di = jj*2 + ee;
                        float gi = sigf(acc[0][n2][di] + bv.x);
                        float gf = sigf(acc[1][n2][di] + bv.y);
                        float gg = tanhfast(acc[2][n2][di] + bv.z);
                        float go = sigf(acc[3][n2][di] + bv.w);
                        int ci = (nh*4 + n2)*4 + jj*2 + ee;
                        float cn = gf * cst[ci] + gi * gg;
                        cst[ci] = cn;
                        float hd = go * tanhfast(cn) * (jj ? gaB : gaA);
                        __half hi = __float2half(hd);
                        int jv = jj ? j2 : j1;
                        *((__half*)(sm + OFF_VH) + e * STV + jv) = hi;
                        *((__half*)(sm + OFF_VL) + e * STV + jv) = __float2half(hd - __half2float(hi));
                    }
                }
            }
        }
        __syncthreads();
    }

    // ================= head =================
    float* ht  = (float*)sm;
    float* hc  = (float*)(sm + 32768);
    float* anc = (float*)(sm + 65536);
    float* lg  = (float*)(sm + 78336);
    for (int it = tid; it < HN * 64; it += NTHR) {
        int jj = it >> 6, e = it & 63;
        ht[it] = __half2float(*((const __half*)(sm + OFF_VH) + e * STV + jj))
               + __half2float(*((const __half*)(sm + OFF_VL) + e * STV + jj));
    }
    for (int it = tid; it < EN * 64; it += NTHR) {
        int q = it >> 6, e = it & 63;
        const float* ar = ancillary + (size_t)(eb + e) * AN;
        float a = b_anc[q];
#pragma unroll
        for (int k = 0; k < AN; k++) a = fmaf(ar[k], W_anc[q * AN + k], a);
        anc[it] = fmaxf(a, 0.f);
    }
    __syncthreads();
    {
        int jh = tid >> 1, hf = tid & 1;
        const float* wc = W_cat + (size_t)jh * (HN + EN);
        float a2[32];
        float bc = b_cat[jh];
#pragma unroll
        for (int c = 0; c < 32; c++) a2[c] = bc;
        for (int jj = 0; jj < HN; jj++) {
            float wv = wc[jj];
            const float* hr = ht + jj * 64 + hf * 32;
#pragma unroll
            for (int c = 0; c < 32; c++) a2[c] = fmaf(wv, hr[c], a2[c]);
        }
        for (int q = 0; q < EN; q++) {
            float wv = wc[HN + q];
            const float* arow = anc + q * 64 + hf * 32;
#pragma unroll
            for (int c = 0; c < 32; c++) a2[c] = fmaf(wv, arow[c], a2[c]);
        }
#pragma unroll
        for (int c = 0; c < 32; c++) hc[jh * 64 + hf * 32 + c] = fmaxf(a2[c], 0.f);
    }
    __syncthreads();
    for (int it = tid; it < ON * 64; it += NTHR) {
        int o = it >> 6, e = it & 63;
        const float* wo = W_out + (size_t)o * HN;
        float a = b_out[o];
#pragma unroll 8
        for (int jj = 0; jj < HN; jj++) a = fmaf(hc[jj * 64 + e], wo[jj], a);
        lg[it] = a;
    }
    __syncthreads();
    if (tid < 64) {
        int e = tid;
        float mx = -1e30f;
        for (int o = 0; o < ON; o++) mx = fmaxf(mx, lg[o * 64 + e]);
        float s = 0.f;
        for (int o = 0; o < ON; o++) s += __expf(lg[o * 64 + e] - mx);
        float inv = __fdividef(1.f, s);
        const float* pr = probs + (size_t)(eb + e) * ON;
        float* yo = out + YH_OFF + (size_t)(eb + e) * ON;
        float yl = 0.f;
        for (int o = 0; o < ON; o++) {
            float y = __expf(lg[o * 64 + e] - mx) * inv;
            yo[o] = y;
            float dd = y - pr[o];
            yl += dd * dd;
        }
        atomicAdd(&g_yloss, yl);
        out[LBL_OFF + eb + e] = (float)labels[eb + e];
    }
}

__global__ void rits_finalize(float* __restrict__ out) {
    __shared__ float s[NTHR];
    int t = threadIdx.x;
    float v = 0.f;
    if (t < TN)
        v = (g_part[1][t] + g_part[2][t] + g_part[3][t]) / (g_part[0][t] + 1e-5f);
    s[t] = v;
    __syncthreads();
    for (int st = NTHR / 2; st > 0; st >>= 1) {
        if (t < st) s[t] += s[t + st];
        __syncthreads();
    }
    if (t == 0) {
        float xl = 0.3f * s[0];
        float yl = g_yloss / (8192.0f + 1e-5f);
        out[0] = xl; out[1] = yl; out[2] = xl + yl;
    }
}

extern "C" void kernel_launch(void* const* d_in, const int* in_sizes, int n_in,
                              void* d_out, int out_size) {
    (void)in_sizes; (void)n_in; (void)out_size;
    const float* values    = (const float*)d_in[0];
    const float* masks     = (const float*)d_in[1];
    const float* deltas    = (const float*)d_in[2];
    const float* probs     = (const float*)d_in[3];
    const float* ancillary = (const float*)d_in[4];
    const int*   labels    = (const int*)  d_in[5];
    const float* W_td_h = (const float*)d_in[6];
    const float* b_td_h = (const float*)d_in[7];
    const float* W_td_x = (const float*)d_in[8];
    const float* b_td_x = (const float*)d_in[9];
    const float* W_hist = (const float*)d_in[10];
    const float* b_hist = (const float*)d_in[11];
    const float* W_feat = (const float*)d_in[12];
    const float* b_feat = (const float*)d_in[13];
    const float* W_comb = (const float*)d_in[14];
    const float* b_comb = (const float*)d_in[15];
    const float* W_ih   = (const float*)d_in[16];
    const float* W_hh   = (const float*)d_in[17];
    const float* b_ih   = (const float*)d_in[18];
    const float* b_hh   = (const float*)d_in[19];
    const float* W_anc  = (const float*)d_in[20];
    const float* b_anc  = (const float*)d_in[21];
    const float* W_cat  = (const float*)d_in[22];
    const float* b_cat  = (const float*)d_in[23];
    const float* W_out  = (const float*)d_in[24];
    const float* b_out  = (const float*)d_in[25];
    float* out = (float*)d_out;

    cudaFuncSetAttribute(rits_main, cudaFuncAttributeMaxDynamicSharedMemorySize, SMEM_TOTAL);
    rits_prep<<<272, NTHR>>>(W_ih, W_hh, b_ih, b_hh);
    rits_main<<<NBLK, NTHR, SMEM_TOTAL>>>(values, masks, deltas, probs, ancillary, labels,
                                          W_td_h, b_td_h, W_td_x, b_td_x, W_hist, b_hist,
                                          W_feat, b_feat, W_comb, b_comb,
                                          W_anc, b_anc, W_cat, b_cat, W_out, b_out, out);
    rits_finalize<<<1, NTHR>>>(out);
}

// round 16
// speedup vs baseline: 2.2362x; 1.2982x over previous
#include <cuda_runtime.h>
#include <cuda_fp16.h>
#include <cstdint>

#define BN 8192
#define TN 223
#define DN 7
#define HN 128
#define EN 50
#define ON 29
#define AN 9
#define NTHR 256
#define NTHRM 512
#define NBLK 128
#define NE 64

#define YH_OFF 3
#define IMP_OFF (3 + BN*ON)
#define LBL_OFF (IMP_OFF + BN*TN*DN)

#define STW 136
#define STE 24
#define STV 152
#define OFF_WH 0
#define OFF_WE 139264
#define OFF_VH 163840
#define OFF_VL 183296
#define OFF_F  202752
#define FXD 0
#define FMD 896
#define FDD 1792
#define FXH 2688
#define FXC 3136
#define FGX 3584
#define FWF 4032
#define FWCB 4081
#define FBH 4179
#define FBF 4186
#define FBC 4193
#define FTDX 4200
#define FBTDX 4207
#define FWHT 4216
#define FRED 5240
#define NFLT 5244
#define SMEM_TOTAL (OFF_F + NFLT*4)

__device__ __align__(16) unsigned char g_wimg[163840];
__device__ float4 g_b4[HN];
__device__ float  g_part[4][TN];
__device__ float  g_yloss;

__device__ __forceinline__ uint32_t smem_u32(const void* p) {
    uint32_t a;
    asm("{ .reg .u64 t; cvta.to.shared.u64 t, %1; cvt.u32.u64 %0, t; }" : "=r"(a) : "l"(p));
    return a;
}
__device__ __forceinline__ void ldsm4(uint32_t& a0, uint32_t& a1, uint32_t& a2, uint32_t& a3, uint32_t ad) {
    asm volatile("ldmatrix.sync.aligned.m8n8.x4.shared.b16 {%0,%1,%2,%3}, [%4];"
                 : "=r"(a0), "=r"(a1), "=r"(a2), "=r"(a3) : "r"(ad));
}
__device__ __forceinline__ void ldsm2(uint32_t& b0, uint32_t& b1, uint32_t ad) {
    asm volatile("ldmatrix.sync.aligned.m8n8.x2.shared.b16 {%0,%1}, [%2];"
                 : "=r"(b0), "=r"(b1) : "r"(ad));
}
__device__ __forceinline__ void mmaop(float* d, uint32_t a0, uint32_t a1, uint32_t a2, uint32_t a3,
                                      uint32_t b0, uint32_t b1) {
    asm volatile("mma.sync.aligned.m16n8k16.row.col.f32.f16.f16.f32 "
                 "{%0,%1,%2,%3}, {%4,%5,%6,%7}, {%8,%9}, {%0,%1,%2,%3};"
                 : "+f"(d[0]), "+f"(d[1]), "+f"(d[2]), "+f"(d[3])
                 : "r"(a0), "r"(a1), "r"(a2), "r"(a3), "r"(b0), "r"(b1));
}
__device__ __forceinline__ float tanhfast(float x) {
    float r; asm("tanh.approx.f32 %0, %1;" : "=f"(r) : "f"(x)); return r;
}
__device__ __forceinline__ float sigf(float x) { return fmaf(tanhfast(0.5f * x), 0.5f, 0.5f); }

__global__ void rits_prep(const float* __restrict__ Wih, const float* __restrict__ Whh,
                          const float* __restrict__ bih, const float* __restrict__ bhh) {
    int i = blockIdx.x * blockDim.x + threadIdx.x;
    if (i < 512 * STW) {
        int r = i / STW, k = i - r * STW;
        ((__half*)g_wimg)[i] = __float2half((k < HN) ? Whh[r * HN + k] : 0.f);
    }
    if (i < 512 * STE) {
        int r = i / STE, c = i - r * STE;
        ((__half*)(g_wimg + OFF_WE))[i] = __float2half((c < 2 * DN) ? Wih[r * 2 * DN + c] : 0.f);
    }
    if (i < HN)
        g_b4[i] = make_float4(bih[i] + bhh[i], bih[HN + i] + bhh[HN + i],
                              bih[2*HN + i] + bhh[2*HN + i], bih[3*HN + i] + bhh[3*HN + i]);
    if (i < 4 * TN) ((float*)g_part)[i] = 0.f;
    if (i == 0) g_yloss = 0.f;
}

__global__ void __launch_bounds__(NTHRM) rits_main(
    const float* __restrict__ values,  const float* __restrict__ masks,
    const float* __restrict__ deltas,  const float* __restrict__ probs,
    const float* __restrict__ ancillary, const int* __restrict__ labels,
    const float* __restrict__ W_td_h,  const float* __restrict__ b_td_h,
    const float* __restrict__ W_td_x,  const float* __restrict__ b_td_x,
    const float* __restrict__ W_hist,  const float* __restrict__ b_hist,
    const float* __restrict__ W_feat,  const float* __restrict__ b_feat,
    const float* __restrict__ W_comb,  const float* __restrict__ b_comb,
    const float* __restrict__ W_anc,   const float* __restrict__ b_anc,
    const float* __restrict__ W_cat,   const float* __restrict__ b_cat,
    const float* __restrict__ W_out,   const float* __restrict__ b_out,
    float* __restrict__ out)
{
    extern __shared__ __align__(16) unsigned char sm[];
    float* F = (float*)(sm + OFF_F);
    const uint32_t sb = smem_u32(sm);
    const int tid = threadIdx.x, lane = tid & 31, w = tid >> 5;
    const int gid = lane >> 2, tig = lane & 3;
    const int jb = 16 * (w & 7);            // M rows within each gate
    const int ntb = (w >> 3) * 4;           // first n-tile of this warp's e-half
    const int eb = blockIdx.x * NE;

    for (int i = tid; i < 163840/16; i += NTHRM) ((uint4*)sm)[i] = ((const uint4*)g_wimg)[i];
    for (int i = tid; i < 38912/16; i += NTHRM) ((uint4*)(sm + OFF_VH))[i] = make_uint4(0,0,0,0);
    if (tid < 49) { int a = tid/7, b = tid%7; F[FWF+tid] = (a==b) ? 0.f : W_feat[tid]; }
    if (tid >= 64 && tid < 162) F[FWCB + tid - 64] = W_comb[tid - 64];
    if (tid >= 192 && tid < 199) {
        int k = tid - 192;
        F[FBH+k] = b_hist[k]; F[FBF+k] = b_feat[k]; F[FBC+k] = b_comb[k];
        F[FTDX+k] = W_td_x[k*DN+k]; F[FBTDX+k] = b_td_x[k];
    }
    if (tid >= 224 && tid < 228) F[FRED + tid - 224] = 0.f;
    for (int i = tid; i < 1024; i += NTHRM) {
        int j = i >> 3, k = i & 7;
        F[FWHT + i] = (k < DN) ? W_hist[k * HN + j] : 0.f;
    }
    if (tid < 448) {
        int k = tid >> 6, e = tid & 63;
        size_t o = (size_t)(eb + e) * TN * DN + k;
        F[FXD+tid] = values[o]; F[FMD+tid] = masks[o]; F[FDD+tid] = deltas[o];
    }

    const int j1 = jb + gid, j2 = j1 + 8;
    float wtdA[DN], wtdB[DN];
#pragma unroll
    for (int k = 0; k < DN; k++) { wtdA[k] = W_td_h[j1*DN+k]; wtdB[k] = W_td_h[j2*DN+k]; }
    const float btdA = b_td_h[j1], btdB = b_td_h[j2];
    const float4 b4a = g_b4[j1], b4b = g_b4[j2];

    uint32_t aW[4], aEx[4];
#pragma unroll
    for (int g = 0; g < 4; g++) {
        aW[g]  = sb + OFF_WH + (uint32_t)((g*128 + jb) + (lane & 15)) * (2*STW) + (lane >> 4) * 16;
        aEx[g] = sb + OFF_WE + (uint32_t)((g*128 + jb) + (lane & 15)) * (2*STE) + (lane >> 4) * 16;
    }
    const uint32_t aVh = sb + OFF_VH + (uint32_t)(lane & 7) * (2*STV) + ((lane >> 3) & 1) * 16;
    const uint32_t aVl = sb + OFF_VL + (uint32_t)(lane & 7) * (2*STV) + ((lane >> 3) & 1) * 16;

    float cst[16];
#pragma unroll
    for (int i = 0; i < 16; i++) cst[i] = 0.f;
    __syncthreads();

    for (int t = 0; t < TN; ++t) {
        const int cur = t & 1, alt = cur ^ 1;

        // ---- x_h scalar (h = hi+lo), 8-way j-split ----
        {
            int e = tid >> 3, q = tid & 7, j0 = q * 16;
            const __half* vh = (const __half*)(sm + OFF_VH) + e * STV + j0;
            const __half* vl = (const __half*)(sm + OFF_VL) + e * STV + j0;
            float a[DN] = {0.f, 0.f, 0.f, 0.f, 0.f, 0.f, 0.f};
#pragma unroll
            for (int bq = 0; bq < 2; bq++) {
                uint4 uh = *(const uint4*)(vh + bq * 8);
                uint4 ul = *(const uint4*)(vl + bq * 8);
                const uint32_t* ph = (const uint32_t*)&uh;
                const uint32_t* pl = (const uint32_t*)&ul;
#pragma unroll
                for (int p2 = 0; p2 < 4; p2++) {
                    float2 fh = __half22float2(*(const __half2*)&ph[p2]);
                    float2 fl = __half22float2(*(const __half2*)&pl[p2]);
                    float h0 = fh.x + fl.x, h1 = fh.y + fl.y;
                    const float* w0 = F + FWHT + (j0 + bq*8 + p2*2) * 8;
#pragma unroll
                    for (int k = 0; k < DN; k++)
                        a[k] = fmaf(w0[k], h0, fmaf(w0[8 + k], h1, a[k]));
                }
            }
#pragma unroll
            for (int k = 0; k < DN; k++) {
                a[k] += __shfl_xor_sync(0xffffffffu, a[k], 1);
                a[k] += __shfl_xor_sync(0xffffffffu, a[k], 2);
                a[k] += __shfl_xor_sync(0xffffffffu, a[k], 4);
            }
            if (q == 0) {
#pragma unroll
                for (int k = 0; k < DN; k++) F[FXH + k*64 + e] = a[k] + F[FBH + k];
            }
        }
        __syncthreads();

        // ---- D1: x_c, gamma_x, l0, l1 ----
        float l0 = 0.f, l1 = 0.f;
        if (tid < 448) {
            int k = tid >> 6;
            float x = F[FXD + cur*448 + tid], m = F[FMD + cur*448 + tid], d = F[FDD + cur*448 + tid];
            float xh = F[FXH + tid];
            F[FXC + tid] = m * x + (1.f - m) * xh;
            F[FGX + tid] = __expf(-fmaxf(d * F[FTDX + k] + F[FBTDX + k], 0.f));
            l0 = m; l1 = m * fabsf(x - xh);
        }
#pragma unroll
        for (int o = 16; o > 0; o >>= 1) {
            l0 += __shfl_down_sync(0xffffffffu, l0, o);
            l1 += __shfl_down_sync(0xffffffffu, l1, o);
        }
        if (lane == 0 && w < 14) { atomicAdd(&F[FRED], l0); atomicAdd(&F[FRED+1], l1); }
        __syncthreads();

        // ---- D2: z, alpha, c_h, c_c, losses, imputation, V extra; prefetch ----
        float l2 = 0.f, l3 = 0.f;
        if (tid < 448) {
            int k = tid >> 6, e = tid & 63;
            float x = F[FXD + cur*448 + tid], m = F[FMD + cur*448 + tid];
            float xh = F[FXH + tid];
            float z = F[FBF + k];
#pragma unroll
            for (int k2 = 0; k2 < DN; k2++) z = fmaf(F[FWF + k*7 + k2], F[FXC + k2*64 + e], z);
            l2 = m * fabsf(x - z);
            float al = F[FBC + k];
#pragma unroll
            for (int k2 = 0; k2 < DN; k2++) {
                al = fmaf(F[FWCB + k*14 + k2], F[FGX + k2*64 + e], al);
                al = fmaf(F[FWCB + k*14 + 7 + k2], F[FMD + cur*448 + k2*64 + e], al);
            }
            float ch = al * z + (1.f - al) * xh;
            l3 = m * fabsf(x - ch);
            float cc = m * x + (1.f - m) * ch;
            out[IMP_OFF + ((size_t)(eb + e) * TN + t) * DN + k] = cc;
            *((__half*)(sm + OFF_VH) + e * STV + 128 + k) = __float2half(cc);
            *((__half*)(sm + OFF_VH) + e * STV + 135 + k) = __float2half(m);
            if (t + 1 < TN) {
                size_t o = ((size_t)(eb + e) * TN + (t + 1)) * DN + k;
                F[FXD + alt*448 + tid] = values[o];
                F[FMD + alt*448 + tid] = masks[o];
                F[FDD + alt*448 + tid] = deltas[o];
            }
        }
#pragma unroll
        for (int o = 16; o > 0; o >>= 1) {
            l2 += __shfl_down_sync(0xffffffffu, l2, o);
            l3 += __shfl_down_sync(0xffffffffu, l3, o);
        }
        if (lane == 0 && w < 14) { atomicAdd(&F[FRED+2], l2); atomicAdd(&F[FRED+3], l3); }
        __syncthreads();

        if (tid == 0) {
            atomicAdd(&g_part[0][t], F[FRED]);   F[FRED] = 0.f;
            atomicAdd(&g_part[1][t], F[FRED+1]); F[FRED+1] = 0.f;
            atomicAdd(&g_part[2][t], F[FRED+2]); F[FRED+2] = 0.f;
            atomicAdd(&g_part[3][t], F[FRED+3]); F[FRED+3] = 0.f;
        }

        // ---- MMA + epilogue: 2 n-quarters of this warp's e-half ----
#pragma unroll 1
        for (int nh = 0; nh < 2; nh++) {
            float acc[4][2][4];
#pragma unroll
            for (int g = 0; g < 4; g++)
#pragma unroll
                for (int n2 = 0; n2 < 2; n2++)
#pragma unroll
                    for (int i = 0; i < 4; i++) acc[g][n2][i] = 0.f;
#pragma unroll 1
            for (int kc = 0; kc < 8; kc++) {
                uint32_t A0[4], A1[4], A2[4], A3[4];
#pragma unroll
                for (int g = 0; g < 4; g++) ldsm4(A0[g], A1[g], A2[g], A3[g], aW[g] + kc * 32);
#pragma unroll
                for (int n2 = 0; n2 < 2; n2++) {
                    int nt = ntb + nh*2 + n2;
                    uint32_t boff = (uint32_t)nt * (16*STV) + kc * 32;
                    uint32_t b0, b1;
                    ldsm2(b0, b1, aVh + boff);
#pragma unroll
                    for (int g = 0; g < 4; g++) mmaop(acc[g][n2], A0[g], A1[g], A2[g], A3[g], b0, b1);
                    ldsm2(b0, b1, aVl + boff);
#pragma unroll
                    for (int g = 0; g < 4; g++) mmaop(acc[g][n2], A0[g], A1[g], A2[g], A3[g], b0, b1);
                }
            }
            {
                uint32_t A0[4], A1[4], A2[4], A3[4];
#pragma unroll
                for (int g = 0; g < 4; g++) ldsm4(A0[g], A1[g], A2[g], A3[g], aEx[g]);
#pragma unroll
                for (int n2 = 0; n2 < 2; n2++) {
                    int nt = ntb + nh*2 + n2;
                    uint32_t b0, b1;
                    ldsm2(b0, b1, aVh + (uint32_t)nt * (16*STV) + 256);
#pragma unroll
                    for (int g = 0; g < 4; g++) mmaop(acc[g][n2], A0[g], A1[g], A2[g], A3[g], b0, b1);
                }
            }
            __syncthreads();
#pragma unroll
            for (int n2 = 0; n2 < 2; n2++) {
#pragma unroll
                for (int ee = 0; ee < 2; ee++) {
                    int e = (ntb + nh*2 + n2) * 8 + 2*tig + ee;
                    float gaA = 1.f, gaB = 1.f;
                    if (t + 1 < TN) {
                        float sA = btdA, sB = btdB;
#pragma unroll
                        for (int k = 0; k < DN; k++) {
                            float dv = F[FDD + alt*448 + k*64 + e];
                            sA = fmaf(wtdA[k], dv, sA);
                            sB = fmaf(wtdB[k], dv, sB);
                        }
                        gaA = __expf(-fmaxf(sA, 0.f));
                        gaB = __expf(-fmaxf(sB, 0.f));
                    }
#pragma unroll
                    for (int jj = 0; jj < 2; jj++) {
                        const float4 bv = jj ? b4b : b4a;
                        int di = jj*2 + ee;
                        float gi = sigf(acc[0][n2][di] + bv.x);
                        float gf = sigf(acc[1][n2][di] + bv.y);
                        float gg = tanhfast(acc[2][n2][di] + bv.z);
                        float go = sigf(acc[3][n2][di] + bv.w);
                        int ci = (nh*2 + n2)*4 + jj*2 + ee;
                        float cn = gf * cst[ci] + gi * gg;
                        cst[ci] = cn;
                        float hd = go * tanhfast(cn) * (jj ? gaB : gaA);
                        __half hi = __float2half(hd);
                        int jv = jj ? j2 : j1;
                        *((__half*)(sm + OFF_VH) + e * STV + jv) = hi;
                        *((__half*)(sm + OFF_VL) + e * STV + jv) = __float2half(hd - __half2float(hi));
                    }
                }
            }
        }
        __syncthreads();
    }

    // ================= head =================
    float* ht  = (float*)sm;
    float* hc  = (float*)(sm + 32768);
    float* anc = (float*)(sm + 65536);
    float* lg  = (float*)(sm + 78336);
    for (int it = tid; it < HN * 64; it += NTHRM) {
        int jj = it >> 6, e = it & 63;
        ht[it] = __half2float(*((const __half*)(sm + OFF_VH) + e * STV + jj))
               + __half2float(*((const __half*)(sm + OFF_VL) + e * STV + jj));
    }
    for (int it = tid; it < EN * 64; it += NTHRM) {
        int q = it >> 6, e = it & 63;
        const float* ar = ancillary + (size_t)(eb + e) * AN;
        float a = b_anc[q];
#pragma unroll
        for (int k = 0; k < AN; k++) a = fmaf(ar[k], W_anc[q * AN + k], a);
        anc[it] = fmaxf(a, 0.f);
    }
    __syncthreads();
    {
        int jh = tid >> 2, qt = tid & 3;
        const float* wc = W_cat + (size_t)jh * (HN + EN);
        float a2[16];
        float bc = b_cat[jh];
#pragma unroll
        for (int c = 0; c < 16; c++) a2[c] = bc;
        for (int jj = 0; jj < HN; jj++) {
            float wv = wc[jj];
            const float* hr = ht + jj * 64 + qt * 16;
#pragma unroll
            for (int c = 0; c < 16; c++) a2[c] = fmaf(wv, hr[c], a2[c]);
        }
        for (int q = 0; q < EN; q++) {
            float wv = wc[HN + q];
            const float* arow = anc + q * 64 + qt * 16;
#pragma unroll
            for (int c = 0; c < 16; c++) a2[c] = fmaf(wv, arow[c], a2[c]);
        }
#pragma unroll
        for (int c = 0; c < 16; c++) hc[jh * 64 + qt * 16 + c] = fmaxf(a2[c], 0.f);
    }
    __syncthreads();
    for (int it = tid; it < ON * 64; it += NTHRM) {
        int o = it >> 6, e = it & 63;
        const float* wo = W_out + (size_t)o * HN;
        float a = b_out[o];
#pragma unroll 8
        for (int jj = 0; jj < HN; jj++) a = fmaf(hc[jj * 64 + e], wo[jj], a);
        lg[it] = a;
    }
    __syncthreads();
    if (tid < 64) {
        int e = tid;
        float mx = -1e30f;
        for (int o = 0; o < ON; o++) mx = fmaxf(mx, lg[o * 64 + e]);
        float s = 0.f;
        for (int o = 0; o < ON; o++) s += __expf(lg[o * 64 + e] - mx);
        float inv = __fdividef(1.f, s);
        const float* pr = probs + (size_t)(eb + e) * ON;
        float* yo = out + YH_OFF + (size_t)(eb + e) * ON;
        float yl = 0.f;
        for (int o = 0; o < ON; o++) {
            float y = __expf(lg[o * 64 + e] - mx) * inv;
            yo[o] = y;
            float dd = y - pr[o];
            yl += dd * dd;
        }
        atomicAdd(&g_yloss, yl);
        out[LBL_OFF + eb + e] = (float)labels[eb + e];
    }
}

__global__ void rits_finalize(float* __restrict__ out) {
    __shared__ float s[NTHR];
    int t = threadIdx.x;
    float v = 0.f;
    if (t < TN)
        v = (g_part[1][t] + g_part[2][t] + g_part[3][t]) / (g_part[0][t] + 1e-5f);
    s[t] = v;
    __syncthreads();
    for (int st = NTHR / 2; st > 0; st >>= 1) {
        if (t < st) s[t] += s[t + st];
        __syncthreads();
    }
    if (t == 0) {
        float xl = 0.3f * s[0];
        float yl = g_yloss / (8192.0f + 1e-5f);
        out[0] = xl; out[1] = yl; out[2] = xl + yl;
    }
}

extern "C" void kernel_launch(void* const* d_in, const int* in_sizes, int n_in,
                              void* d_out, int out_size) {
    (void)in_sizes; (void)n_in; (void)out_size;
    const float* values    = (const float*)d_in[0];
    const float* masks     = (const float*)d_in[1];
    const float* deltas    = (const float*)d_in[2];
    const float* probs     = (const float*)d_in[3];
    const float* ancillary = (const float*)d_in[4];
    const int*   labels    = (const int*)  d_in[5];
    const float* W_td_h = (const float*)d_in[6];
    const float* b_td_h = (const float*)d_in[7];
    const float* W_td_x = (const float*)d_in[8];
    const float* b_td_x = (const float*)d_in[9];
    const float* W_hist = (const float*)d_in[10];
    const float* b_hist = (const float*)d_in[11];
    const float* W_feat = (const float*)d_in[12];
    const float* b_feat = (const float*)d_in[13];
    const float* W_comb = (const float*)d_in[14];
    const float* b_comb = (const float*)d_in[15];
    const float* W_ih   = (const float*)d_in[16];
    const float* W_hh   = (const float*)d_in[17];
    const float* b_ih   = (const float*)d_in[18];
    const float* b_hh   = (const float*)d_in[19];
    const float* W_anc  = (const float*)d_in[20];
    const float* b_anc  = (const float*)d_in[21];
    const float* W_cat  = (const float*)d_in[22];
    const float* b_cat  = (const float*)d_in[23];
    const float* W_out  = (const float*)d_in[24];
    const float* b_out  = (const float*)d_in[25];
    float* out = (float*)d_out;

    cudaFuncSetAttribute(rits_main, cudaFuncAttributeMaxDynamicSharedMemorySize, SMEM_TOTAL);
    rits_prep<<<272, NTHR>>>(W_ih, W_hh, b_ih, b_hh);
    rits_main<<<NBLK, NTHRM, SMEM_TOTAL>>>(values, masks, deltas, probs, ancillary, labels,
                                           W_td_h, b_td_h, W_td_x, b_td_x, W_hist, b_hist,
                                           W_feat, b_feat, W_comb, b_comb,
                                           W_anc, b_anc, W_cat, b_cat, W_out, b_out, out);
    rits_finalize<<<1, NTHR>>>(out);
}